// round 2
// baseline (speedup 1.0000x reference)
#include <cuda_runtime.h>
#include <math.h>

#define D_MODEL 1024
#define N_HEADS 16
#define D_KV    64
#define BATCH   2
#define SEQ     2048
#define M_TOTAL (BATCH*SEQ)     // 4096

// ---------------- scratch (device globals: no runtime allocation) ----------
__device__ float g_Q[(size_t)BATCH*N_HEADS*SEQ*D_KV];   // [b,h,s,d]
__device__ float g_K[(size_t)BATCH*N_HEADS*SEQ*D_KV];
__device__ float g_V[(size_t)BATCH*N_HEADS*SEQ*D_KV];
__device__ float g_O[(size_t)BATCH*SEQ*D_MODEL];        // [b,s,h*64+d]
__device__ float g_cos[SEQ*(D_KV/2)];                   // [pos][pair]
__device__ float g_sin[SEQ*(D_KV/2)];

// ---------------- RoPE tables (fp64, tiny) ---------------------------------
__global__ void rope_table_kernel() {
    int idx = blockIdx.x * blockDim.x + threadIdx.x;   // 2048*32
    int p   = idx & 31;
    int pos = idx >> 5;
    double freq = pow(10000.0, -(double)(2 * p) / 64.0);
    double ang  = (double)pos * freq;
    g_cos[idx] = (float)cos(ang);
    g_sin[idx] = (float)sin(ang);
}

// ---------------- GEMM: C[m][n] = sum_k A[m][k] * W[n][k] -------------------
// BM=BN=128, BK=8, 256 threads, 8x8 microtile, double-buffered smem.
// MODE 0: plain row-major output  (output projection)
// MODE 1: [b,h,s,d] output, no RoPE (V)
// MODE 2: [b,h,s,d] output, RoPE   (Q, K)
template<int MODE>
__global__ __launch_bounds__(256)
void gemm128_kernel(const float* __restrict__ A, const float* __restrict__ W,
                    float* __restrict__ C, const int* __restrict__ tp)
{
    __shared__ float As[2][8][128];
    __shared__ float Ws[2][8][128];

    const int tid = threadIdx.x;
    const int tx  = tid & 15;          // 16 col-groups
    const int ty  = tid >> 4;          // 16 row-groups
    const int m0  = blockIdx.y * 128;
    const int n0  = blockIdx.x * 128;

    const int row = tid >> 1;          // 0..127 (tile row for loading)
    const int kq  = (tid & 1) * 4;     // 0 or 4

    const float* gA = A + (size_t)(m0 + row) * D_MODEL + kq;
    const float* gW = W + (size_t)(n0 + row) * D_MODEL + kq;

    float acc[8][8];
#pragma unroll
    for (int i = 0; i < 8; i++)
#pragma unroll
        for (int j = 0; j < 8; j++) acc[i][j] = 0.f;

    float4 ra = *(const float4*)gA;
    float4 rw = *(const float4*)gW;
    As[0][kq+0][row] = ra.x; As[0][kq+1][row] = ra.y;
    As[0][kq+2][row] = ra.z; As[0][kq+3][row] = ra.w;
    Ws[0][kq+0][row] = rw.x; Ws[0][kq+1][row] = rw.y;
    Ws[0][kq+2][row] = rw.z; Ws[0][kq+3][row] = rw.w;
    __syncthreads();

    const int KT = D_MODEL / 8;        // 128
    for (int kt = 0; kt < KT; kt++) {
        const int cur = kt & 1;
        if (kt < KT - 1) {
            ra = *(const float4*)(gA + (kt + 1) * 8);
            rw = *(const float4*)(gW + (kt + 1) * 8);
        }
#pragma unroll
        for (int kk = 0; kk < 8; kk++) {
            float4 a0 = *(const float4*)&As[cur][kk][ty * 4];
            float4 a1 = *(const float4*)&As[cur][kk][ty * 4 + 64];
            float4 b0 = *(const float4*)&Ws[cur][kk][tx * 4];
            float4 b1 = *(const float4*)&Ws[cur][kk][tx * 4 + 64];
            float av[8] = {a0.x,a0.y,a0.z,a0.w,a1.x,a1.y,a1.z,a1.w};
            float bv[8] = {b0.x,b0.y,b0.z,b0.w,b1.x,b1.y,b1.z,b1.w};
#pragma unroll
            for (int i = 0; i < 8; i++)
#pragma unroll
                for (int j = 0; j < 8; j++)
                    acc[i][j] += av[i] * bv[j];
        }
        if (kt < KT - 1) {
            const int nb = cur ^ 1;
            As[nb][kq+0][row] = ra.x; As[nb][kq+1][row] = ra.y;
            As[nb][kq+2][row] = ra.z; As[nb][kq+3][row] = ra.w;
            Ws[nb][kq+0][row] = rw.x; Ws[nb][kq+1][row] = rw.y;
            Ws[nb][kq+2][row] = rw.z; Ws[nb][kq+3][row] = rw.w;
            __syncthreads();
        }
    }

    // epilogue
#pragma unroll
    for (int ig = 0; ig < 2; ig++) {
#pragma unroll
        for (int ii = 0; ii < 4; ii++) {
            const int i = ig * 4 + ii;
            const int m = m0 + ig * 64 + ty * 4 + ii;
            const int srow = m & (SEQ - 1);
            const int bb   = m >> 11;
#pragma unroll
            for (int jg = 0; jg < 2; jg++) {
                const int j = jg * 4;
                const int n = n0 + jg * 64 + tx * 4;
                float v0 = acc[i][j], v1 = acc[i][j+1];
                float v2 = acc[i][j+2], v3 = acc[i][j+3];
                if (MODE == 2) {
                    const int posv = tp[srow];
                    const int d0 = n & 63;           // multiple of 4
                    const int p0 = d0 >> 1;
                    const float c0 = g_cos[posv * 32 + p0];
                    const float s0 = g_sin[posv * 32 + p0];
                    const float c1 = g_cos[posv * 32 + p0 + 1];
                    const float s1 = g_sin[posv * 32 + p0 + 1];
                    const float e0 = v0 * c0 - v1 * s0;
                    const float o0 = v1 * c0 + v0 * s0;
                    const float e1 = v2 * c1 - v3 * s1;
                    const float o1 = v3 * c1 + v2 * s1;
                    v0 = e0; v1 = o0; v2 = e1; v3 = o1;
                }
                if (MODE == 0) {
                    *(float4*)&C[(size_t)m * D_MODEL + n] =
                        make_float4(v0, v1, v2, v3);
                } else {
                    const int h = n >> 6, d = n & 63;
                    const size_t idx =
                        ((size_t)(bb * N_HEADS + h) * SEQ + srow) * D_KV + d;
                    *(float4*)&C[idx] = make_float4(v0, v1, v2, v3);
                }
            }
        }
    }
}

// ---------------- flash attention (causal, online softmax) -----------------
// grid: (S/128, H, B), block 128 threads, 1 thread = 1 query row.
__global__ __launch_bounds__(128)
void flash_attn_kernel(const float* __restrict__ Q, const float* __restrict__ K,
                       const float* __restrict__ V, float* __restrict__ O)
{
    extern __shared__ float sm[];
    float* k_sh = sm;                 // 64*64
    float* v_sh = sm + 4096;          // 64*64
    float* s_sh = sm + 8192;          // 128*65

    const int tid = threadIdx.x;
    const int q0  = blockIdx.x * 128;
    const int h   = blockIdx.y;
    const int b   = blockIdx.z;
    const int bh  = b * N_HEADS + h;
    const int qr  = q0 + tid;

    const float* Qb = Q + (size_t)bh * SEQ * D_KV;
    const float* Kb = K + (size_t)bh * SEQ * D_KV;
    const float* Vb = V + (size_t)bh * SEQ * D_KV;

    float q[64];
#pragma unroll
    for (int dd = 0; dd < 16; dd++) {
        float4 t = *(const float4*)(Qb + (size_t)qr * D_KV + dd * 4);
        q[dd*4+0] = t.x * 0.125f; q[dd*4+1] = t.y * 0.125f;
        q[dd*4+2] = t.z * 0.125f; q[dd*4+3] = t.w * 0.125f;
    }

    float acc[64];
#pragma unroll
    for (int d = 0; d < 64; d++) acc[d] = 0.f;
    float mrun = -1e30f, lrun = 0.f;

    const int ktiles = blockIdx.x * 2 + 2;   // keys up to q0+127
    for (int kt = 0; kt < ktiles; kt++) {
        const int kbase = kt * 64;
        // cooperative tile load: 64x64 floats each = 1024 float4s
#pragma unroll
        for (int i = 0; i < 8; i++) {
            const int fi = tid + i * 128;
            *(float4*)(k_sh + fi * 4) =
                *(const float4*)(Kb + (size_t)kbase * D_KV + fi * 4);
            *(float4*)(v_sh + fi * 4) =
                *(const float4*)(Vb + (size_t)kbase * D_KV + fi * 4);
        }
        __syncthreads();

        int jhi = qr - kbase + 1;
        if (jhi > 64) jhi = 64;
        if (jhi > 0) {
            float* srow = s_sh + tid * 65;
            float tmax = -1e30f;
            for (int j = 0; j < jhi; j++) {
                const float4* k4 = (const float4*)(k_sh + j * 64);
                float s0 = 0.f, s1 = 0.f, s2 = 0.f, s3 = 0.f;
#pragma unroll
                for (int dd = 0; dd < 16; dd++) {
                    float4 kv = k4[dd];
                    s0 += q[dd*4+0] * kv.x;
                    s1 += q[dd*4+1] * kv.y;
                    s2 += q[dd*4+2] * kv.z;
                    s3 += q[dd*4+3] * kv.w;
                }
                const float s = (s0 + s1) + (s2 + s3);
                srow[j] = s;
                tmax = fmaxf(tmax, s);
            }
            const float mnew  = fmaxf(mrun, tmax);
            const float scale = __expf(mrun - mnew);
            lrun *= scale;
#pragma unroll
            for (int d = 0; d < 64; d++) acc[d] *= scale;
            for (int j = 0; j < jhi; j++) {
                const float p = __expf(srow[j] - mnew);
                lrun += p;
                const float4* v4 = (const float4*)(v_sh + j * 64);
#pragma unroll
                for (int dd = 0; dd < 16; dd++) {
                    float4 vv = v4[dd];
                    acc[dd*4+0] += p * vv.x;
                    acc[dd*4+1] += p * vv.y;
                    acc[dd*4+2] += p * vv.z;
                    acc[dd*4+3] += p * vv.w;
                }
            }
            mrun = mnew;
        }
        __syncthreads();
    }

    const float inv = 1.f / lrun;
    float* orow = O + ((size_t)(b * SEQ + qr)) * D_MODEL + h * D_KV;
#pragma unroll
    for (int dd = 0; dd < 16; dd++) {
        *(float4*)(orow + dd * 4) = make_float4(acc[dd*4+0] * inv,
                                                acc[dd*4+1] * inv,
                                                acc[dd*4+2] * inv,
                                                acc[dd*4+3] * inv);
    }
}

// ---------------- host launcher ---------------------------------------------
extern "C" void kernel_launch(void* const* d_in, const int* in_sizes, int n_in,
                              void* d_out, int out_size)
{
    const float* x  = (const float*)d_in[0];
    const float* wq = (const float*)d_in[1];
    const float* wk = (const float*)d_in[2];
    const float* wv = (const float*)d_in[3];
    const float* wo = (const float*)d_in[4];
    const int*   tp = (const int*)d_in[5];
    float* out = (float*)d_out;

    float *Qp, *Kp, *Vp, *Op;
    cudaGetSymbolAddress((void**)&Qp, g_Q);
    cudaGetSymbolAddress((void**)&Kp, g_K);
    cudaGetSymbolAddress((void**)&Vp, g_V);
    cudaGetSymbolAddress((void**)&Op, g_O);

    // 1. RoPE tables
    rope_table_kernel<<<SEQ * 32 / 256, 256>>>();

    // 2-4. QKV projections (+RoPE for Q,K) into [b,h,s,d]
    dim3 ggrid(D_MODEL / 128, M_TOTAL / 128);   // (8, 32)
    gemm128_kernel<2><<<ggrid, 256>>>(x, wq, Qp, tp);
    gemm128_kernel<2><<<ggrid, 256>>>(x, wk, Kp, tp);
    gemm128_kernel<1><<<ggrid, 256>>>(x, wv, Vp, tp);

    // 5. flash attention
    const int smem = (4096 + 4096 + 128 * 65) * sizeof(float);  // 66048 B
    cudaFuncSetAttribute(flash_attn_kernel,
                         cudaFuncAttributeMaxDynamicSharedMemorySize, smem);
    dim3 agrid(SEQ / 128, N_HEADS, BATCH);      // (16,16,2)
    flash_attn_kernel<<<agrid, 128, smem>>>(Qp, Kp, Vp, Op);

    // 6. output projection
    gemm128_kernel<0><<<ggrid, 256>>>(Op, wo, out, tp);
}

// round 4
// speedup vs baseline: 2.7134x; 2.7134x over previous
#include <cuda_runtime.h>
#include <cuda_bf16.h>
#include <math.h>
#include <cstdint>

#define D_MODEL 1024
#define N_HEADS 16
#define D_KV    64
#define BATCH   2
#define SEQ     2048
#define M_TOTAL (BATCH*SEQ)     // 4096

typedef __nv_bfloat16 bf16;

// ---------------- scratch (device globals) ----------------------------------
__device__ bf16 g_xh[(size_t)M_TOTAL*D_MODEL],  g_xl[(size_t)M_TOTAL*D_MODEL];
__device__ bf16 g_wqh[(size_t)D_MODEL*D_MODEL], g_wql[(size_t)D_MODEL*D_MODEL];
__device__ bf16 g_wkh[(size_t)D_MODEL*D_MODEL], g_wkl[(size_t)D_MODEL*D_MODEL];
__device__ bf16 g_wvh[(size_t)D_MODEL*D_MODEL], g_wvl[(size_t)D_MODEL*D_MODEL];
__device__ bf16 g_woh[(size_t)D_MODEL*D_MODEL], g_wol[(size_t)D_MODEL*D_MODEL];
__device__ bf16 g_Qh[(size_t)M_TOTAL*D_MODEL],  g_Ql[(size_t)M_TOTAL*D_MODEL];   // [b,h,s,d]
__device__ bf16 g_Kh[(size_t)M_TOTAL*D_MODEL],  g_Kl[(size_t)M_TOTAL*D_MODEL];
__device__ bf16 g_Vh[(size_t)M_TOTAL*D_MODEL],  g_Vl[(size_t)M_TOTAL*D_MODEL];
__device__ bf16 g_Oh[(size_t)M_TOTAL*D_MODEL],  g_Ol[(size_t)M_TOTAL*D_MODEL];   // [b*s, h*64+d]
__device__ float g_cos[SEQ*(D_KV/2)];
__device__ float g_sin[SEQ*(D_KV/2)];

// ---------------- mma / ldmatrix helpers (base-target legal) -----------------
__device__ __forceinline__ void ldsm4(uint32_t* r, uint32_t a) {
    asm volatile("ldmatrix.sync.aligned.m8n8.x4.shared.b16 {%0,%1,%2,%3}, [%4];"
        : "=r"(r[0]), "=r"(r[1]), "=r"(r[2]), "=r"(r[3]) : "r"(a));
}
__device__ __forceinline__ void ldsm4t(uint32_t* r, uint32_t a) {
    asm volatile("ldmatrix.sync.aligned.m8n8.x4.trans.shared.b16 {%0,%1,%2,%3}, [%4];"
        : "=r"(r[0]), "=r"(r[1]), "=r"(r[2]), "=r"(r[3]) : "r"(a));
}
__device__ __forceinline__ void mma16816(float* c, const uint32_t* a, const uint32_t* b) {
    asm volatile("mma.sync.aligned.m16n8k16.row.col.f32.bf16.bf16.f32 "
        "{%0,%1,%2,%3}, {%4,%5,%6,%7}, {%8,%9}, {%0,%1,%2,%3};"
        : "+f"(c[0]), "+f"(c[1]), "+f"(c[2]), "+f"(c[3])
        : "r"(a[0]), "r"(a[1]), "r"(a[2]), "r"(a[3]), "r"(b[0]), "r"(b[1]));
}
__device__ __forceinline__ void packhl(float x, float y, uint32_t& h, uint32_t& l) {
    __nv_bfloat162 hh = __floats2bfloat162_rn(x, y);
    float2 hf = __bfloat1622float2(hh);
    __nv_bfloat162 ll = __floats2bfloat162_rn(x - hf.x, y - hf.y);
    h = *reinterpret_cast<uint32_t*>(&hh);
    l = *reinterpret_cast<uint32_t*>(&ll);
}

// ---------------- fp32 -> bf16 hi/lo split -----------------------------------
__global__ void split_kernel(const float* __restrict__ src, bf16* __restrict__ hi,
                             bf16* __restrict__ lo, int n) {
    int i = (blockIdx.x * blockDim.x + threadIdx.x) * 4;
    if (i >= n) return;
    float4 v = *(const float4*)(src + i);
    __nv_bfloat162 h0 = __floats2bfloat162_rn(v.x, v.y);
    __nv_bfloat162 h1 = __floats2bfloat162_rn(v.z, v.w);
    float2 f0 = __bfloat1622float2(h0), f1 = __bfloat1622float2(h1);
    __nv_bfloat162 l0 = __floats2bfloat162_rn(v.x - f0.x, v.y - f0.y);
    __nv_bfloat162 l1 = __floats2bfloat162_rn(v.z - f1.x, v.w - f1.y);
    *(uint32_t*)(hi + i)     = *(uint32_t*)&h0;
    *(uint32_t*)(hi + i + 2) = *(uint32_t*)&h1;
    *(uint32_t*)(lo + i)     = *(uint32_t*)&l0;
    *(uint32_t*)(lo + i + 2) = *(uint32_t*)&l1;
}

// ---------------- RoPE tables ------------------------------------------------
__global__ void rope_table_kernel() {
    int idx = blockIdx.x * blockDim.x + threadIdx.x;   // 2048*32
    int p   = idx & 31;
    int pos = idx >> 5;
    double freq = pow(10000.0, -(double)(2 * p) / 64.0);
    double ang  = (double)pos * freq;
    g_cos[idx] = (float)cos(ang);
    g_sin[idx] = (float)sin(ang);
}

// ---------------- HMMA bf16x3 GEMM: C[m][n] = sum_k A[m][k]*B[n][k] ----------
// MODE 0: fp32 row-major out; 1: V hi/lo [b,h,s,d]; 2: Q (RoPE, x0.125) hi/lo;
// MODE 3: K (RoPE) hi/lo.
#define G_RS    80                  // smem row stride bytes (32 bf16 + pad)
#define G_TILE  (128*G_RS)          // 10240
#define G_STAGE (4*G_TILE)          // 40960

template<int MODE>
__global__ __launch_bounds__(256, 1)
void gemm_mma(const bf16* __restrict__ Ah, const bf16* __restrict__ Al,
              const bf16* __restrict__ Bh, const bf16* __restrict__ Bl,
              float* __restrict__ Cf, bf16* __restrict__ Ch, bf16* __restrict__ Cl,
              const int* __restrict__ tp)
{
    extern __shared__ char sm[];
    const uint32_t smb = (uint32_t)__cvta_generic_to_shared(sm);
    const int tid = threadIdx.x, lane = tid & 31, wid = tid >> 5;
    const int wm = wid >> 2, wn = wid & 3;
    const int m0 = blockIdx.y * 128, n0 = blockIdx.x * 128;

    const int lr = tid >> 1, lh = tid & 1;
    const char* pA0 = (const char*)(Ah + (size_t)(m0 + lr) * D_MODEL);
    const char* pA1 = (const char*)(Al + (size_t)(m0 + lr) * D_MODEL);
    const char* pB0 = (const char*)(Bh + (size_t)(n0 + lr) * D_MODEL);
    const char* pB1 = (const char*)(Bl + (size_t)(n0 + lr) * D_MODEL);
    char* srow = sm + lr * G_RS + lh * 32;

    float acc[4][4][4];
#pragma unroll
    for (int i = 0; i < 4; i++)
#pragma unroll
        for (int j = 0; j < 4; j++)
#pragma unroll
            for (int k = 0; k < 4; k++) acc[i][j][k] = 0.f;

    uint4 buf[4][2];

    // prologue: tile 0
    {
        const int cb = lh * 32;
        buf[0][0] = *(const uint4*)(pA0 + cb); buf[0][1] = *(const uint4*)(pA0 + cb + 16);
        buf[1][0] = *(const uint4*)(pA1 + cb); buf[1][1] = *(const uint4*)(pA1 + cb + 16);
        buf[2][0] = *(const uint4*)(pB0 + cb); buf[2][1] = *(const uint4*)(pB0 + cb + 16);
        buf[3][0] = *(const uint4*)(pB1 + cb); buf[3][1] = *(const uint4*)(pB1 + cb + 16);
#pragma unroll
        for (int t = 0; t < 4; t++) {
            *(uint4*)(srow + t * G_TILE)      = buf[t][0];
            *(uint4*)(srow + t * G_TILE + 16) = buf[t][1];
        }
    }
    __syncthreads();

    const int KT = D_MODEL / 32;   // 32
    for (int kt = 0; kt < KT; kt++) {
        if (kt + 1 < KT) {
            const int cb = (kt + 1) * 64 + lh * 32;
            buf[0][0] = *(const uint4*)(pA0 + cb); buf[0][1] = *(const uint4*)(pA0 + cb + 16);
            buf[1][0] = *(const uint4*)(pA1 + cb); buf[1][1] = *(const uint4*)(pA1 + cb + 16);
            buf[2][0] = *(const uint4*)(pB0 + cb); buf[2][1] = *(const uint4*)(pB0 + cb + 16);
            buf[3][0] = *(const uint4*)(pB1 + cb); buf[3][1] = *(const uint4*)(pB1 + cb + 16);
        }
        const uint32_t stb = smb + (kt & 1) * G_STAGE;
#pragma unroll
        for (int kk = 0; kk < 2; kk++) {
            uint32_t ah[4][4], al[4][4], bh[2][4], bl[2][4];
#pragma unroll
            for (int mi = 0; mi < 4; mi++) {
                uint32_t a = stb + (wm * 64 + mi * 16 + (lane & 15)) * G_RS
                           + kk * 32 + (lane >> 4) * 16;
                ldsm4(ah[mi], a);
                ldsm4(al[mi], a + G_TILE);
            }
#pragma unroll
            for (int L = 0; L < 2; L++) {
                uint32_t a = stb + 2 * G_TILE
                           + (wn * 32 + L * 16 + (lane & 7) + ((lane >> 4) & 1) * 8) * G_RS
                           + kk * 32 + ((lane >> 3) & 1) * 16;
                ldsm4(bh[L], a);
                ldsm4(bl[L], a + G_TILE);
            }
#pragma unroll
            for (int mi = 0; mi < 4; mi++)
#pragma unroll
                for (int nf = 0; nf < 4; nf++) {
                    const uint32_t* bph = &bh[nf >> 1][(nf & 1) * 2];
                    const uint32_t* bpl = &bl[nf >> 1][(nf & 1) * 2];
                    mma16816(acc[mi][nf], ah[mi], bph);
                    mma16816(acc[mi][nf], al[mi], bph);
                    mma16816(acc[mi][nf], ah[mi], bpl);
                }
        }
        if (kt + 1 < KT) {
            char* dst = srow + ((kt + 1) & 1) * G_STAGE;
#pragma unroll
            for (int t = 0; t < 4; t++) {
                *(uint4*)(dst + t * G_TILE)      = buf[t][0];
                *(uint4*)(dst + t * G_TILE + 16) = buf[t][1];
            }
        }
        __syncthreads();
    }

    // epilogue
#pragma unroll
    for (int mi = 0; mi < 4; mi++)
#pragma unroll
        for (int nf = 0; nf < 4; nf++) {
            const int row0 = m0 + wm * 64 + mi * 16 + (lane >> 2);
            const int col  = n0 + wn * 32 + (nf >> 1) * 16 + (nf & 1) * 8 + 2 * (lane & 3);
            float v0 = acc[mi][nf][0], v1 = acc[mi][nf][1];
            float v2 = acc[mi][nf][2], v3 = acc[mi][nf][3];
            if (MODE >= 2) {  // RoPE
                const int p = (col & 63) >> 1;
                const int pos0 = tp[row0 & (SEQ - 1)];
                const int pos1 = tp[(row0 + 8) & (SEQ - 1)];
                const float c0 = g_cos[pos0 * 32 + p], s0 = g_sin[pos0 * 32 + p];
                const float c1 = g_cos[pos1 * 32 + p], s1 = g_sin[pos1 * 32 + p];
                float e0 = v0 * c0 - v1 * s0, o0 = v1 * c0 + v0 * s0;
                float e1 = v2 * c1 - v3 * s1, o1 = v3 * c1 + v2 * s1;
                v0 = e0; v1 = o0; v2 = e1; v3 = o1;
                if (MODE == 2) { v0 *= 0.125f; v1 *= 0.125f; v2 *= 0.125f; v3 *= 0.125f; }
            }
            if (MODE == 0) {
                *(float2*)(Cf + (size_t)row0 * D_MODEL + col)       = make_float2(v0, v1);
                *(float2*)(Cf + (size_t)(row0 + 8) * D_MODEL + col) = make_float2(v2, v3);
            } else {
                const int hh = col >> 6, d = col & 63;
                const int bb = row0 >> 11, ss = row0 & (SEQ - 1);
                size_t i0 = ((size_t)(bb * N_HEADS + hh) * SEQ + ss) * D_KV + d;
                size_t i1 = i0 + 8 * D_KV;
                uint32_t h0, l0, h1, l1;
                packhl(v0, v1, h0, l0);
                packhl(v2, v3, h1, l1);
                *(uint32_t*)(Ch + i0) = h0; *(uint32_t*)(Cl + i0) = l0;
                *(uint32_t*)(Ch + i1) = h1; *(uint32_t*)(Cl + i1) = l1;
            }
        }
}

// ---------------- tensor-core flash attention (causal, no-max softmax) -------
// block 256 thr = 8 warps, each warp 16 q-rows; key tiles of 64.
#define A_RS    144                 // 64 bf16 + pad
#define A_KT    (64*A_RS)           // 9216
#define A_STAGE (4*A_KT)            // 36864
#define QL_OFF  18432               // Q lo tile offset
#define ST_OFF  36864               // KV stages start

__global__ __launch_bounds__(256, 1)
void attn_mma(const bf16* __restrict__ Qh_, const bf16* __restrict__ Ql_,
              const bf16* __restrict__ Kh_, const bf16* __restrict__ Kl_,
              const bf16* __restrict__ Vh_, const bf16* __restrict__ Vl_,
              bf16* __restrict__ Oh_, bf16* __restrict__ Ol_)
{
    extern __shared__ char sm[];
    const uint32_t smb = (uint32_t)__cvta_generic_to_shared(sm);
    const int tid = threadIdx.x, lane = tid & 31, wid = tid >> 5;
    const int qt = gridDim.x - 1 - blockIdx.x;      // heavy blocks first
    const int q0 = qt * 128;
    const int h = blockIdx.y, b = blockIdx.z;
    const size_t hb = (size_t)(b * N_HEADS + h) * SEQ * D_KV;
    const int nt = 2 * qt + 2;

    const bf16* Qh = Qh_ + hb; const bf16* Ql = Ql_ + hb;
    const bf16* Kh = Kh_ + hb; const bf16* Kl = Kl_ + hb;
    const bf16* Vh = Vh_ + hb; const bf16* Vl = Vl_ + hb;

    // load Q tile (hi+lo)
    {
        const int r = tid >> 1;
        const char* gqh = (const char*)(Qh + (size_t)(q0 + r) * D_KV);
        const char* gql = (const char*)(Ql + (size_t)(q0 + r) * D_KV);
        char* sq = sm + r * A_RS;
#pragma unroll
        for (int i = 0; i < 4; i++) {
            const int c = (tid & 1) * 64 + i * 16;
            *(uint4*)(sq + c)          = *(const uint4*)(gqh + c);
            *(uint4*)(sq + QL_OFF + c) = *(const uint4*)(gql + c);
        }
    }

    // KV loader mapping
    const int kr = tid >> 2;
    const int kc = (tid & 3) * 32;
    uint4 kbuf[4][2];
#define KV_LOAD(KT_) do { \
        const size_t roff = (size_t)((KT_) * 64 + kr) * D_KV; \
        const char* t0 = (const char*)(Kh + roff); \
        const char* t1 = (const char*)(Kl + roff); \
        const char* t2 = (const char*)(Vh + roff); \
        const char* t3 = (const char*)(Vl + roff); \
        kbuf[0][0] = *(const uint4*)(t0 + kc); kbuf[0][1] = *(const uint4*)(t0 + kc + 16); \
        kbuf[1][0] = *(const uint4*)(t1 + kc); kbuf[1][1] = *(const uint4*)(t1 + kc + 16); \
        kbuf[2][0] = *(const uint4*)(t2 + kc); kbuf[2][1] = *(const uint4*)(t2 + kc + 16); \
        kbuf[3][0] = *(const uint4*)(t3 + kc); kbuf[3][1] = *(const uint4*)(t3 + kc + 16); \
    } while (0)
#define KV_STORE(ST_) do { \
        char* dst = sm + ST_OFF + (ST_) * A_STAGE + kr * A_RS + kc; \
        _Pragma("unroll") \
        for (int t = 0; t < 4; t++) { \
            *(uint4*)(dst + t * A_KT)      = kbuf[t][0]; \
            *(uint4*)(dst + t * A_KT + 16) = kbuf[t][1]; \
        } \
    } while (0)

    KV_LOAD(0);
    KV_STORE(0);
    __syncthreads();

    // Q fragments
    uint32_t qh[4][4], ql[4][4];
#pragma unroll
    for (int kk = 0; kk < 4; kk++) {
        uint32_t a = smb + (wid * 16 + (lane & 15)) * A_RS + kk * 32 + (lane >> 4) * 16;
        ldsm4(qh[kk], a);
        ldsm4(ql[kk], a + QL_OFF);
    }

    float oacc[8][4];
#pragma unroll
    for (int i = 0; i < 8; i++)
#pragma unroll
        for (int j = 0; j < 4; j++) oacc[i][j] = 0.f;
    float ls0 = 0.f, ls1 = 0.f;
    const int wr0 = q0 + wid * 16;

    for (int kt = 0; kt < nt; kt++) {
        if (kt + 1 < nt) KV_LOAD(kt + 1);
        const uint32_t stb = smb + ST_OFF + (kt & 1) * A_STAGE;
        const int kbase = kt * 64;

        if (kbase <= wr0 + 15) {
            float sacc[8][4];
#pragma unroll
            for (int i = 0; i < 8; i++)
#pragma unroll
                for (int j = 0; j < 4; j++) sacc[i][j] = 0.f;

            // S = Q K^T (bf16x3)
#pragma unroll
            for (int kk = 0; kk < 4; kk++) {
                uint32_t kbh[4][4], kbl[4][4];
#pragma unroll
                for (int L = 0; L < 4; L++) {
                    uint32_t a = stb + (L * 16 + (lane & 7) + ((lane >> 4) & 1) * 8) * A_RS
                               + kk * 32 + ((lane >> 3) & 1) * 16;
                    ldsm4(kbh[L], a);
                    ldsm4(kbl[L], a + A_KT);
                }
#pragma unroll
                for (int nf = 0; nf < 8; nf++) {
                    const uint32_t* bph = &kbh[nf >> 1][(nf & 1) * 2];
                    const uint32_t* bpl = &kbl[nf >> 1][(nf & 1) * 2];
                    mma16816(sacc[nf], qh[kk], bph);
                    mma16816(sacc[nf], ql[kk], bph);
                    mma16816(sacc[nf], qh[kk], bpl);
                }
            }

            // mask + exp (no max subtraction; scores bounded)
            const bool needm = (kbase + 63 > wr0);
#pragma unroll
            for (int nf = 0; nf < 8; nf++)
#pragma unroll
                for (int j = 0; j < 4; j++) {
                    float p = __expf(sacc[nf][j]);
                    if (needm) {
                        const int key = kbase + nf * 8 + 2 * (lane & 3) + (j & 1);
                        const int row = wr0 + (lane >> 2) + (j >> 1) * 8;
                        if (key > row) p = 0.f;
                    }
                    sacc[nf][j] = p;
                    if (j < 2) ls0 += p; else ls1 += p;
                }

            // O += P V (bf16x3)
#pragma unroll
            for (int kk2 = 0; kk2 < 4; kk2++) {
                uint32_t vh[4][4], vl[4][4];
#pragma unroll
                for (int dL = 0; dL < 4; dL++) {
                    uint32_t a = stb + 2 * A_KT
                               + (kk2 * 16 + (lane & 7) + ((lane >> 3) & 1) * 8) * A_RS
                               + dL * 32 + ((lane >> 4) & 1) * 16;
                    ldsm4t(vh[dL], a);
                    ldsm4t(vl[dL], a + A_KT);
                }
                uint32_t ph[4], pl[4];
                packhl(sacc[2*kk2][0],   sacc[2*kk2][1],   ph[0], pl[0]);
                packhl(sacc[2*kk2][2],   sacc[2*kk2][3],   ph[1], pl[1]);
                packhl(sacc[2*kk2+1][0], sacc[2*kk2+1][1], ph[2], pl[2]);
                packhl(sacc[2*kk2+1][2], sacc[2*kk2+1][3], ph[3], pl[3]);
#pragma unroll
                for (int df = 0; df < 8; df++) {
                    const uint32_t* bph = &vh[df >> 1][(df & 1) * 2];
                    const uint32_t* bpl = &vl[df >> 1][(df & 1) * 2];
                    mma16816(oacc[df], ph, bph);
                    mma16816(oacc[df], pl, bph);
                    mma16816(oacc[df], ph, bpl);
                }
            }
        }

        if (kt + 1 < nt) KV_STORE((kt + 1) & 1);
        __syncthreads();
    }

    // reduce row sums across quad
    ls0 += __shfl_xor_sync(0xffffffffu, ls0, 1);
    ls0 += __shfl_xor_sync(0xffffffffu, ls0, 2);
    ls1 += __shfl_xor_sync(0xffffffffu, ls1, 1);
    ls1 += __shfl_xor_sync(0xffffffffu, ls1, 2);
    const float inv0 = 1.f / ls0, inv1 = 1.f / ls1;

    const int row0 = q0 + wid * 16 + (lane >> 2);
#pragma unroll
    for (int df = 0; df < 8; df++) {
        const int d = df * 8 + 2 * (lane & 3);
        const float v0 = oacc[df][0] * inv0, v1 = oacc[df][1] * inv0;
        const float v2 = oacc[df][2] * inv1, v3 = oacc[df][3] * inv1;
        const size_t i0 = (size_t)(b * SEQ + row0) * D_MODEL + h * D_KV + d;
        const size_t i1 = i0 + (size_t)8 * D_MODEL;
        uint32_t h0, l0, h1, l1;
        packhl(v0, v1, h0, l0);
        packhl(v2, v3, h1, l1);
        *(uint32_t*)(Oh_ + i0) = h0; *(uint32_t*)(Ol_ + i0) = l0;
        *(uint32_t*)(Oh_ + i1) = h1; *(uint32_t*)(Ol_ + i1) = l1;
    }
}

// ---------------- host launcher ----------------------------------------------
extern "C" void kernel_launch(void* const* d_in, const int* in_sizes, int n_in,
                              void* d_out, int out_size)
{
    const float* x  = (const float*)d_in[0];
    const float* wq = (const float*)d_in[1];
    const float* wk = (const float*)d_in[2];
    const float* wv = (const float*)d_in[3];
    const float* wo = (const float*)d_in[4];
    const int*   tp = (const int*)d_in[5];
    float* out = (float*)d_out;

    bf16 *xh, *xl, *wqh, *wql, *wkh, *wkl, *wvh, *wvl, *woh, *wol;
    bf16 *Qh, *Ql, *Kh, *Kl, *Vh, *Vl, *Oh, *Ol;
    cudaGetSymbolAddress((void**)&xh, g_xh);   cudaGetSymbolAddress((void**)&xl, g_xl);
    cudaGetSymbolAddress((void**)&wqh, g_wqh); cudaGetSymbolAddress((void**)&wql, g_wql);
    cudaGetSymbolAddress((void**)&wkh, g_wkh); cudaGetSymbolAddress((void**)&wkl, g_wkl);
    cudaGetSymbolAddress((void**)&wvh, g_wvh); cudaGetSymbolAddress((void**)&wvl, g_wvl);
    cudaGetSymbolAddress((void**)&woh, g_woh); cudaGetSymbolAddress((void**)&wol, g_wol);
    cudaGetSymbolAddress((void**)&Qh, g_Qh);   cudaGetSymbolAddress((void**)&Ql, g_Ql);
    cudaGetSymbolAddress((void**)&Kh, g_Kh);   cudaGetSymbolAddress((void**)&Kl, g_Kl);
    cudaGetSymbolAddress((void**)&Vh, g_Vh);   cudaGetSymbolAddress((void**)&Vl, g_Vl);
    cudaGetSymbolAddress((void**)&Oh, g_Oh);   cudaGetSymbolAddress((void**)&Ol, g_Ol);

    const int gemm_smem = 2 * G_STAGE;                        // 81920
    const int attn_smem = ST_OFF + 2 * A_STAGE;               // 110592
    cudaFuncSetAttribute(gemm_mma<0>, cudaFuncAttributeMaxDynamicSharedMemorySize, gemm_smem);
    cudaFuncSetAttribute(gemm_mma<1>, cudaFuncAttributeMaxDynamicSharedMemorySize, gemm_smem);
    cudaFuncSetAttribute(gemm_mma<2>, cudaFuncAttributeMaxDynamicSharedMemorySize, gemm_smem);
    cudaFuncSetAttribute(gemm_mma<3>, cudaFuncAttributeMaxDynamicSharedMemorySize, gemm_smem);
    cudaFuncSetAttribute(attn_mma,    cudaFuncAttributeMaxDynamicSharedMemorySize, attn_smem);

    // splits + tables
    split_kernel<<<M_TOTAL * D_MODEL / 1024, 256>>>(x, xh, xl, M_TOTAL * D_MODEL);
    split_kernel<<<D_MODEL * D_MODEL / 1024, 256>>>(wq, wqh, wql, D_MODEL * D_MODEL);
    split_kernel<<<D_MODEL * D_MODEL / 1024, 256>>>(wk, wkh, wkl, D_MODEL * D_MODEL);
    split_kernel<<<D_MODEL * D_MODEL / 1024, 256>>>(wv, wvh, wvl, D_MODEL * D_MODEL);
    split_kernel<<<D_MODEL * D_MODEL / 1024, 256>>>(wo, woh, wol, D_MODEL * D_MODEL);
    rope_table_kernel<<<SEQ * 32 / 256, 256>>>();

    // projections
    dim3 ggrid(D_MODEL / 128, M_TOTAL / 128);   // (8, 32)
    gemm_mma<2><<<ggrid, 256, gemm_smem>>>(xh, xl, wqh, wql, nullptr, Qh, Ql, tp);
    gemm_mma<3><<<ggrid, 256, gemm_smem>>>(xh, xl, wkh, wkl, nullptr, Kh, Kl, tp);
    gemm_mma<1><<<ggrid, 256, gemm_smem>>>(xh, xl, wvh, wvl, nullptr, Vh, Vl, tp);

    // attention
    dim3 agrid(SEQ / 128, N_HEADS, BATCH);      // (16,16,2)
    attn_mma<<<agrid, 256, attn_smem>>>(Qh, Ql, Kh, Kl, Vh, Vl, Oh, Ol);

    // output projection
    gemm_mma<0><<<ggrid, 256, gemm_smem>>>(Oh, Ol, woh, wol, out, nullptr, nullptr, tp);
}

// round 7
// speedup vs baseline: 3.6266x; 1.3365x over previous
#include <cuda_runtime.h>
#include <cuda_fp16.h>
#include <math.h>
#include <cstdint>

#define D_MODEL 1024
#define N_HEADS 16
#define D_KV    64
#define BATCH   2
#define SEQ     2048
#define M_TOTAL (BATCH*SEQ)     // 4096

// ---------------- scratch (device globals) ----------------------------------
__device__ half g_xh[(size_t)M_TOTAL*D_MODEL],  g_xl[(size_t)M_TOTAL*D_MODEL];
__device__ half g_wqh[(size_t)D_MODEL*D_MODEL];
__device__ half g_wkh[(size_t)D_MODEL*D_MODEL];
__device__ half g_wvh[(size_t)D_MODEL*D_MODEL];
__device__ half g_woh[(size_t)D_MODEL*D_MODEL];
__device__ half g_Qh[(size_t)M_TOTAL*D_MODEL],  g_Ql[(size_t)M_TOTAL*D_MODEL]; // [b,h,s,d]
__device__ half g_Kh[(size_t)M_TOTAL*D_MODEL];                                  // [b,h,s,d]
__device__ half g_Vh[(size_t)M_TOTAL*D_MODEL];
__device__ half g_Oh[(size_t)M_TOTAL*D_MODEL],  g_Ol[(size_t)M_TOTAL*D_MODEL]; // [b*s, h*64+d]
__device__ float g_cos[SEQ*(D_KV/2)];
__device__ float g_sin[SEQ*(D_KV/2)];

// ---------------- mma / ldmatrix helpers -------------------------------------
__device__ __forceinline__ void ldsm4(uint32_t* r, uint32_t a) {
    asm volatile("ldmatrix.sync.aligned.m8n8.x4.shared.b16 {%0,%1,%2,%3}, [%4];"
        : "=r"(r[0]), "=r"(r[1]), "=r"(r[2]), "=r"(r[3]) : "r"(a));
}
__device__ __forceinline__ void ldsm4t(uint32_t* r, uint32_t a) {
    asm volatile("ldmatrix.sync.aligned.m8n8.x4.trans.shared.b16 {%0,%1,%2,%3}, [%4];"
        : "=r"(r[0]), "=r"(r[1]), "=r"(r[2]), "=r"(r[3]) : "r"(a));
}
__device__ __forceinline__ void mma16816(float* c, const uint32_t* a, const uint32_t* b) {
    asm volatile("mma.sync.aligned.m16n8k16.row.col.f32.f16.f16.f32 "
        "{%0,%1,%2,%3}, {%4,%5,%6,%7}, {%8,%9}, {%0,%1,%2,%3};"
        : "+f"(c[0]), "+f"(c[1]), "+f"(c[2]), "+f"(c[3])
        : "r"(a[0]), "r"(a[1]), "r"(a[2]), "r"(a[3]), "r"(b[0]), "r"(b[1]));
}
// fp32 pair -> fp16 hi + fp16 lo words
__device__ __forceinline__ void packhl(float x, float y, uint32_t& h, uint32_t& l) {
    half2 hh = __floats2half2_rn(x, y);
    float2 hf = __half22float2(hh);
    half2 ll = __floats2half2_rn(x - hf.x, y - hf.y);
    h = *reinterpret_cast<uint32_t*>(&hh);
    l = *reinterpret_cast<uint32_t*>(&ll);
}
__device__ __forceinline__ uint32_t pack1(float x, float y) {
    half2 hh = __floats2half2_rn(x, y);
    return *reinterpret_cast<uint32_t*>(&hh);
}

// ---------------- fp32 -> fp16 hi/lo split (x) -------------------------------
__global__ void split_kernel(const float* __restrict__ src, half* __restrict__ hi,
                             half* __restrict__ lo, int n) {
    int i = (blockIdx.x * blockDim.x + threadIdx.x) * 4;
    if (i >= n) return;
    float4 v = *(const float4*)(src + i);
    uint32_t h0, l0, h1, l1;
    packhl(v.x, v.y, h0, l0);
    packhl(v.z, v.w, h1, l1);
    *(uint32_t*)(hi + i)     = h0; *(uint32_t*)(hi + i + 2) = h1;
    *(uint32_t*)(lo + i)     = l0; *(uint32_t*)(lo + i + 2) = l1;
}

// ---------------- fp32 -> fp16 convert (4 weights, one launch) ---------------
__global__ void cvtw_kernel(const float* __restrict__ w0, const float* __restrict__ w1,
                            const float* __restrict__ w2, const float* __restrict__ w3,
                            half* __restrict__ o0, half* __restrict__ o1,
                            half* __restrict__ o2, half* __restrict__ o3) {
    const int y = blockIdx.y;
    const float* s = (y == 0) ? w0 : (y == 1) ? w1 : (y == 2) ? w2 : w3;
    half* d = (y == 0) ? o0 : (y == 1) ? o1 : (y == 2) ? o2 : o3;
    int i = (blockIdx.x * blockDim.x + threadIdx.x) * 4;
    float4 v = *(const float4*)(s + i);
    *(uint32_t*)(d + i)     = pack1(v.x, v.y);
    *(uint32_t*)(d + i + 2) = pack1(v.z, v.w);
}

// ---------------- RoPE tables ------------------------------------------------
__global__ void rope_table_kernel() {
    int idx = blockIdx.x * blockDim.x + threadIdx.x;   // 2048*32
    int p   = idx & 31;
    int pos = idx >> 5;
    double freq = pow(10000.0, -(double)(2 * p) / 64.0);
    double ang  = (double)pos * freq;
    g_cos[idx] = (float)cos(ang);
    g_sin[idx] = (float)sin(ang);
}

// ---------------- HMMA fp16x2 GEMM: C[m][n] = sum_k A[m][k]*B[n][k] ----------
// A = Ah + Al (fp16 split, exact to 22 bits); B plain fp16.
// qkv=1: grid.z selects {0:Q(RoPE,x0.125,hi/lo) 1:K(RoPE,fp16) 2:V(fp16)}
// qkv=0: fp32 row-major out (O projection).
#define G_RS    80                  // smem row stride bytes (32 fp16 + pad)
#define G_TILE  (128*G_RS)          // 10240
#define G_STAGE (3*G_TILE)          // 30720

__global__ __launch_bounds__(256, 1)
void gemm_mma(const half* __restrict__ Ah, const half* __restrict__ Al,
              const half* __restrict__ B0, const half* __restrict__ B1,
              const half* __restrict__ B2,
              float* __restrict__ Cf, half* __restrict__ Qh, half* __restrict__ Ql,
              half* __restrict__ Kh, half* __restrict__ Vh,
              const int* __restrict__ tp, int qkv)
{
    extern __shared__ char sm[];
    const uint32_t smb = (uint32_t)__cvta_generic_to_shared(sm);
    const int tid = threadIdx.x, lane = tid & 31, wid = tid >> 5;
    const int wm = wid >> 2, wn = wid & 3;
    const int m0 = blockIdx.y * 128, n0 = blockIdx.x * 128;
    const int z  = blockIdx.z;
    const half* W = qkv ? ((z == 0) ? B0 : (z == 1) ? B1 : B2) : B0;
    const int mode = qkv ? ((z == 0) ? 2 : (z == 1) ? 3 : 1) : 0;

    const int lr = tid >> 1, lh = tid & 1;
    const char* pA0 = (const char*)(Ah + (size_t)(m0 + lr) * D_MODEL);
    const char* pA1 = (const char*)(Al + (size_t)(m0 + lr) * D_MODEL);
    const char* pB0 = (const char*)(W  + (size_t)(n0 + lr) * D_MODEL);
    char* srow = sm + lr * G_RS + lh * 32;

    float acc[4][4][4];
#pragma unroll
    for (int i = 0; i < 4; i++)
#pragma unroll
        for (int j = 0; j < 4; j++)
#pragma unroll
            for (int k = 0; k < 4; k++) acc[i][j][k] = 0.f;

    uint4 buf[3][2];
    {
        const int cb = lh * 32;
        buf[0][0] = *(const uint4*)(pA0 + cb); buf[0][1] = *(const uint4*)(pA0 + cb + 16);
        buf[1][0] = *(const uint4*)(pA1 + cb); buf[1][1] = *(const uint4*)(pA1 + cb + 16);
        buf[2][0] = *(const uint4*)(pB0 + cb); buf[2][1] = *(const uint4*)(pB0 + cb + 16);
#pragma unroll
        for (int t = 0; t < 3; t++) {
            *(uint4*)(srow + t * G_TILE)      = buf[t][0];
            *(uint4*)(srow + t * G_TILE + 16) = buf[t][1];
        }
    }
    __syncthreads();

    const int KT = D_MODEL / 32;   // 32
    for (int kt = 0; kt < KT; kt++) {
        if (kt + 1 < KT) {
            const int cb = (kt + 1) * 64 + lh * 32;
            buf[0][0] = *(const uint4*)(pA0 + cb); buf[0][1] = *(const uint4*)(pA0 + cb + 16);
            buf[1][0] = *(const uint4*)(pA1 + cb); buf[1][1] = *(const uint4*)(pA1 + cb + 16);
            buf[2][0] = *(const uint4*)(pB0 + cb); buf[2][1] = *(const uint4*)(pB0 + cb + 16);
        }
        const uint32_t stb = smb + (kt & 1) * G_STAGE;
#pragma unroll
        for (int kk = 0; kk < 2; kk++) {
            uint32_t ah[4][4], al[4][4], bh[2][4];
#pragma unroll
            for (int mi = 0; mi < 4; mi++) {
                uint32_t a = stb + (wm * 64 + mi * 16 + (lane & 15)) * G_RS
                           + kk * 32 + (lane >> 4) * 16;
                ldsm4(ah[mi], a);
                ldsm4(al[mi], a + G_TILE);
            }
#pragma unroll
            for (int L = 0; L < 2; L++) {
                uint32_t a = stb + 2 * G_TILE
                           + (wn * 32 + L * 16 + (lane & 7) + ((lane >> 4) & 1) * 8) * G_RS
                           + kk * 32 + ((lane >> 3) & 1) * 16;
                ldsm4(bh[L], a);
            }
#pragma unroll
            for (int mi = 0; mi < 4; mi++)
#pragma unroll
                for (int nf = 0; nf < 4; nf++) {
                    const uint32_t* bp = &bh[nf >> 1][(nf & 1) * 2];
                    mma16816(acc[mi][nf], ah[mi], bp);
                    mma16816(acc[mi][nf], al[mi], bp);
                }
        }
        if (kt + 1 < KT) {
            char* dst = srow + ((kt + 1) & 1) * G_STAGE;
#pragma unroll
            for (int t = 0; t < 3; t++) {
                *(uint4*)(dst + t * G_TILE)      = buf[t][0];
                *(uint4*)(dst + t * G_TILE + 16) = buf[t][1];
            }
        }
        __syncthreads();
    }

    // epilogue
#pragma unroll
    for (int mi = 0; mi < 4; mi++)
#pragma unroll
        for (int nf = 0; nf < 4; nf++) {
            const int row0 = m0 + wm * 64 + mi * 16 + (lane >> 2);
            const int col  = n0 + wn * 32 + (nf >> 1) * 16 + (nf & 1) * 8 + 2 * (lane & 3);
            float v0 = acc[mi][nf][0], v1 = acc[mi][nf][1];
            float v2 = acc[mi][nf][2], v3 = acc[mi][nf][3];
            if (mode >= 2) {  // RoPE
                const int p = (col & 63) >> 1;
                const int pos0 = tp[row0 & (SEQ - 1)];
                const int pos1 = tp[(row0 + 8) & (SEQ - 1)];
                const float c0 = g_cos[pos0 * 32 + p], s0 = g_sin[pos0 * 32 + p];
                const float c1 = g_cos[pos1 * 32 + p], s1 = g_sin[pos1 * 32 + p];
                float e0 = v0 * c0 - v1 * s0, o0 = v1 * c0 + v0 * s0;
                float e1 = v2 * c1 - v3 * s1, o1 = v3 * c1 + v2 * s1;
                v0 = e0; v1 = o0; v2 = e1; v3 = o1;
                if (mode == 2) { v0 *= 0.125f; v1 *= 0.125f; v2 *= 0.125f; v3 *= 0.125f; }
            }
            if (mode == 0) {
                *(float2*)(Cf + (size_t)row0 * D_MODEL + col)       = make_float2(v0, v1);
                *(float2*)(Cf + (size_t)(row0 + 8) * D_MODEL + col) = make_float2(v2, v3);
            } else {
                const int hh = col >> 6, d = col & 63;
                const int bb = row0 >> 11, ss = row0 & (SEQ - 1);
                size_t i0 = ((size_t)(bb * N_HEADS + hh) * SEQ + ss) * D_KV + d;
                size_t i1 = i0 + 8 * D_KV;
                if (mode == 2) {
                    uint32_t h0, l0, h1, l1;
                    packhl(v0, v1, h0, l0);
                    packhl(v2, v3, h1, l1);
                    *(uint32_t*)(Qh + i0) = h0; *(uint32_t*)(Ql + i0) = l0;
                    *(uint32_t*)(Qh + i1) = h1; *(uint32_t*)(Ql + i1) = l1;
                } else if (mode == 3) {
                    *(uint32_t*)(Kh + i0) = pack1(v0, v1);
                    *(uint32_t*)(Kh + i1) = pack1(v2, v3);
                } else {
                    *(uint32_t*)(Vh + i0) = pack1(v0, v1);
                    *(uint32_t*)(Vh + i1) = pack1(v2, v3);
                }
            }
        }
}

// ---------------- tensor-core flash attention (causal, shifted-exp softmax) --
// block 256 thr = 8 warps, each warp 16 q-rows; key tiles of 64.
#define A_RS    144                 // 64 fp16 + pad
#define A_KT    (64*A_RS)           // 9216
#define A_STAGE (2*A_KT)            // 18432 (Kh, Vh)
#define QL_OFF  18432               // Q lo tile offset (128*144)
#define ST_OFF  36864               // KV stages start

__global__ __launch_bounds__(256, 1)
void attn_mma(const half* __restrict__ Qh_, const half* __restrict__ Ql_,
              const half* __restrict__ Kh_, const half* __restrict__ Vh_,
              half* __restrict__ Oh_, half* __restrict__ Ol_)
{
    extern __shared__ char sm[];
    const uint32_t smb = (uint32_t)__cvta_generic_to_shared(sm);
    const int tid = threadIdx.x, lane = tid & 31, wid = tid >> 5;
    const int qt = gridDim.x - 1 - blockIdx.x;      // heavy blocks first
    const int q0 = qt * 128;
    const int h = blockIdx.y, b = blockIdx.z;
    const size_t hb = (size_t)(b * N_HEADS + h) * SEQ * D_KV;
    const int nt = 2 * qt + 2;

    const half* Qh = Qh_ + hb; const half* Ql = Ql_ + hb;
    const half* Kh = Kh_ + hb; const half* Vh = Vh_ + hb;

    // load Q tile (hi+lo)
    {
        const int r = tid >> 1;
        const char* gqh = (const char*)(Qh + (size_t)(q0 + r) * D_KV);
        const char* gql = (const char*)(Ql + (size_t)(q0 + r) * D_KV);
        char* sq = sm + r * A_RS;
#pragma unroll
        for (int i = 0; i < 4; i++) {
            const int c = (tid & 1) * 64 + i * 16;
            *(uint4*)(sq + c)          = *(const uint4*)(gqh + c);
            *(uint4*)(sq + QL_OFF + c) = *(const uint4*)(gql + c);
        }
    }

    // KV loader mapping: 4 threads per row, 32B each (row = 128B)
    const int kr = tid >> 2;
    const int kc = (tid & 3) * 32;
    uint4 kbuf[2][2];
#define KV_LOAD(KT_) do { \
        const size_t roff = (size_t)((KT_) * 64 + kr) * D_KV; \
        const char* t0 = (const char*)(Kh + roff); \
        const char* t1 = (const char*)(Vh + roff); \
        kbuf[0][0] = *(const uint4*)(t0 + kc); kbuf[0][1] = *(const uint4*)(t0 + kc + 16); \
        kbuf[1][0] = *(const uint4*)(t1 + kc); kbuf[1][1] = *(const uint4*)(t1 + kc + 16); \
    } while (0)
#define KV_STORE(ST_) do { \
        char* dst = sm + ST_OFF + (ST_) * A_STAGE + kr * A_RS + kc; \
        *(uint4*)(dst)             = kbuf[0][0]; \
        *(uint4*)(dst + 16)        = kbuf[0][1]; \
        *(uint4*)(dst + A_KT)      = kbuf[1][0]; \
        *(uint4*)(dst + A_KT + 16) = kbuf[1][1]; \
    } while (0)

    KV_LOAD(0);
    KV_STORE(0);
    __syncthreads();

    // Q fragments
    uint32_t qh[4][4], ql[4][4];
#pragma unroll
    for (int kk = 0; kk < 4; kk++) {
        uint32_t a = smb + (wid * 16 + (lane & 15)) * A_RS + kk * 32 + (lane >> 4) * 16;
        ldsm4(qh[kk], a);
        ldsm4(ql[kk], a + QL_OFF);
    }

    float oacc[8][4];
#pragma unroll
    for (int i = 0; i < 8; i++)
#pragma unroll
        for (int j = 0; j < 4; j++) oacc[i][j] = 0.f;
    float ls0 = 0.f, ls1 = 0.f;
    const int wr0 = q0 + wid * 16;

    for (int kt = 0; kt < nt; kt++) {
        if (kt + 1 < nt) KV_LOAD(kt + 1);
        const uint32_t stb = smb + ST_OFF + (kt & 1) * A_STAGE;
        const int kbase = kt * 64;

        if (kbase <= wr0 + 15) {
            float sacc[8][4];
#pragma unroll
            for (int i = 0; i < 8; i++)
#pragma unroll
                for (int j = 0; j < 4; j++) sacc[i][j] = 0.f;

            // S = (Qh+Ql) Kh^T
#pragma unroll
            for (int kk = 0; kk < 4; kk++) {
                uint32_t kbh[4][4];
#pragma unroll
                for (int L = 0; L < 4; L++) {
                    uint32_t a = stb + (L * 16 + (lane & 7) + ((lane >> 4) & 1) * 8) * A_RS
                               + kk * 32 + ((lane >> 3) & 1) * 16;
                    ldsm4(kbh[L], a);
                }
#pragma unroll
                for (int nf = 0; nf < 8; nf++) {
                    const uint32_t* bp = &kbh[nf >> 1][(nf & 1) * 2];
                    mma16816(sacc[nf], qh[kk], bp);
                    mma16816(sacc[nf], ql[kk], bp);
                }
            }

            // mask + shifted exp (p = e^(s-6); shift cancels in normalization)
            const bool needm = (kbase + 63 > wr0);
#pragma unroll
            for (int nf = 0; nf < 8; nf++)
#pragma unroll
                for (int j = 0; j < 4; j++) {
                    float p = __expf(sacc[nf][j] - 6.0f);
                    if (needm) {
                        const int key = kbase + nf * 8 + 2 * (lane & 3) + (j & 1);
                        const int row = wr0 + (lane >> 2) + (j >> 1) * 8;
                        if (key > row) p = 0.f;
                    }
                    sacc[nf][j] = p;
                    if (j < 2) ls0 += p; else ls1 += p;
                }

            // O += (Ph+Pl) Vh
#pragma unroll
            for (int kk2 = 0; kk2 < 4; kk2++) {
                uint32_t vh[4][4];
#pragma unroll
                for (int dL = 0; dL < 4; dL++) {
                    uint32_t a = stb + A_KT
                               + (kk2 * 16 + (lane & 7) + ((lane >> 3) & 1) * 8) * A_RS
                               + dL * 32 + ((lane >> 4) & 1) * 16;
                    ldsm4t(vh[dL], a);
                }
                uint32_t ph[4], pl[4];
                packhl(sacc[2*kk2][0],   sacc[2*kk2][1],   ph[0], pl[0]);
                packhl(sacc[2*kk2][2],   sacc[2*kk2][3],   ph[1], pl[1]);
                packhl(sacc[2*kk2+1][0], sacc[2*kk2+1][1], ph[2], pl[2]);
                packhl(sacc[2*kk2+1][2], sacc[2*kk2+1][3], ph[3], pl[3]);
#pragma unroll
                for (int df = 0; df < 8; df++) {
                    const uint32_t* bp = &vh[df >> 1][(df & 1) * 2];
                    mma16816(oacc[df], ph, bp);
                    mma16816(oacc[df], pl, bp);
                }
            }
        }

        if (kt + 1 < nt) KV_STORE((kt + 1) & 1);
        __syncthreads();
    }

    // reduce row sums across quad
    ls0 += __shfl_xor_sync(0xffffffffu, ls0, 1);
    ls0 += __shfl_xor_sync(0xffffffffu, ls0, 2);
    ls1 += __shfl_xor_sync(0xffffffffu, ls1, 1);
    ls1 += __shfl_xor_sync(0xffffffffu, ls1, 2);
    const float inv0 = 1.f / ls0, inv1 = 1.f / ls1;

    const int row0 = q0 + wid * 16 + (lane >> 2);
#pragma unroll
    for (int df = 0; df < 8; df++) {
        const int d = df * 8 + 2 * (lane & 3);
        const float v0 = oacc[df][0] * inv0, v1 = oacc[df][1] * inv0;
        const float v2 = oacc[df][2] * inv1, v3 = oacc[df][3] * inv1;
        const size_t i0 = (size_t)(b * SEQ + row0) * D_MODEL + h * D_KV + d;
        const size_t i1 = i0 + (size_t)8 * D_MODEL;
        uint32_t h0, l0, h1, l1;
        packhl(v0, v1, h0, l0);
        packhl(v2, v3, h1, l1);
        *(uint32_t*)(Oh_ + i0) = h0; *(uint32_t*)(Ol_ + i0) = l0;
        *(uint32_t*)(Oh_ + i1) = h1; *(uint32_t*)(Ol_ + i1) = l1;
    }
}

// ---------------- host launcher ----------------------------------------------
extern "C" void kernel_launch(void* const* d_in, const int* in_sizes, int n_in,
                              void* d_out, int out_size)
{
    const float* x  = (const float*)d_in[0];
    const float* wq = (const float*)d_in[1];
    const float* wk = (const float*)d_in[2];
    const float* wv = (const float*)d_in[3];
    const float* wo = (const float*)d_in[4];
    const int*   tp = (const int*)d_in[5];
    float* out = (float*)d_out;

    half *xh, *xl, *wqh, *wkh, *wvh, *woh;
    half *Qh, *Ql, *Kh, *Vh, *Oh, *Ol;
    cudaGetSymbolAddress((void**)&xh, g_xh);   cudaGetSymbolAddress((void**)&xl, g_xl);
    cudaGetSymbolAddress((void**)&wqh, g_wqh); cudaGetSymbolAddress((void**)&wkh, g_wkh);
    cudaGetSymbolAddress((void**)&wvh, g_wvh); cudaGetSymbolAddress((void**)&woh, g_woh);
    cudaGetSymbolAddress((void**)&Qh, g_Qh);   cudaGetSymbolAddress((void**)&Ql, g_Ql);
    cudaGetSymbolAddress((void**)&Kh, g_Kh);   cudaGetSymbolAddress((void**)&Vh, g_Vh);
    cudaGetSymbolAddress((void**)&Oh, g_Oh);   cudaGetSymbolAddress((void**)&Ol, g_Ol);

    const int gemm_smem = 2 * G_STAGE;                        // 61440
    const int attn_smem = ST_OFF + 2 * A_STAGE;               // 73728
    cudaFuncSetAttribute(gemm_mma, cudaFuncAttributeMaxDynamicSharedMemorySize, gemm_smem);
    cudaFuncSetAttribute(attn_mma, cudaFuncAttributeMaxDynamicSharedMemorySize, attn_smem);

    // splits / converts / tables (3 launches)
    split_kernel<<<M_TOTAL * D_MODEL / 1024, 256>>>(x, xh, xl, M_TOTAL * D_MODEL);
    cvtw_kernel<<<dim3(D_MODEL * D_MODEL / 1024, 4), 256>>>(wq, wk, wv, wo,
                                                            wqh, wkh, wvh, woh);
    rope_table_kernel<<<SEQ * 32 / 256, 256>>>();

    // fused QKV projections (one launch)
    dim3 qkvgrid(D_MODEL / 128, M_TOTAL / 128, 3);   // (8, 32, 3)
    gemm_mma<<<qkvgrid, 256, gemm_smem>>>(xh, xl, wqh, wkh, wvh,
                                          nullptr, Qh, Ql, Kh, Vh, tp, 1);

    // attention
    dim3 agrid(SEQ / 128, N_HEADS, BATCH);           // (16,16,2)
    attn_mma<<<agrid, 256, attn_smem>>>(Qh, Ql, Kh, Vh, Oh, Ol);

    // output projection
    dim3 ogrid(D_MODEL / 128, M_TOTAL / 128, 1);
    gemm_mma<<<ogrid, 256, gemm_smem>>>(Oh, Ol, woh, nullptr, nullptr,
                                        out, nullptr, nullptr, nullptr, nullptr, tp, 0);
}

// round 8
// speedup vs baseline: 4.0478x; 1.1161x over previous
#include <cuda_runtime.h>
#include <cuda_fp16.h>
#include <math.h>
#include <cstdint>

#define D_MODEL 1024
#define N_HEADS 16
#define D_KV    64
#define BATCH   2
#define SEQ     2048
#define M_TOTAL (BATCH*SEQ)     // 4096

// ---------------- scratch (device globals) ----------------------------------
__device__ half g_xh[(size_t)M_TOTAL*D_MODEL],  g_xl[(size_t)M_TOTAL*D_MODEL];
__device__ half g_wqh[(size_t)D_MODEL*D_MODEL];
__device__ half g_wkh[(size_t)D_MODEL*D_MODEL];
__device__ half g_wvh[(size_t)D_MODEL*D_MODEL];
__device__ half g_woh[(size_t)D_MODEL*D_MODEL];
__device__ half g_Qh[(size_t)M_TOTAL*D_MODEL],  g_Ql[(size_t)M_TOTAL*D_MODEL]; // [b,h,s,d]
__device__ half g_Kh[(size_t)M_TOTAL*D_MODEL];                                  // [b,h,s,d]
__device__ half g_Vh[(size_t)M_TOTAL*D_MODEL];
__device__ half g_Oh[(size_t)M_TOTAL*D_MODEL],  g_Ol[(size_t)M_TOTAL*D_MODEL]; // [b*s, h*64+d]
__device__ float g_cos[SEQ*(D_KV/2)];
__device__ float g_sin[SEQ*(D_KV/2)];

// ---------------- mma / ldmatrix / cp.async helpers --------------------------
__device__ __forceinline__ void ldsm4(uint32_t* r, uint32_t a) {
    asm volatile("ldmatrix.sync.aligned.m8n8.x4.shared.b16 {%0,%1,%2,%3}, [%4];"
        : "=r"(r[0]), "=r"(r[1]), "=r"(r[2]), "=r"(r[3]) : "r"(a));
}
__device__ __forceinline__ void ldsm4t(uint32_t* r, uint32_t a) {
    asm volatile("ldmatrix.sync.aligned.m8n8.x4.trans.shared.b16 {%0,%1,%2,%3}, [%4];"
        : "=r"(r[0]), "=r"(r[1]), "=r"(r[2]), "=r"(r[3]) : "r"(a));
}
__device__ __forceinline__ void mma16816(float* c, const uint32_t* a, const uint32_t* b) {
    asm volatile("mma.sync.aligned.m16n8k16.row.col.f32.f16.f16.f32 "
        "{%0,%1,%2,%3}, {%4,%5,%6,%7}, {%8,%9}, {%0,%1,%2,%3};"
        : "+f"(c[0]), "+f"(c[1]), "+f"(c[2]), "+f"(c[3])
        : "r"(a[0]), "r"(a[1]), "r"(a[2]), "r"(a[3]), "r"(b[0]), "r"(b[1]));
}
__device__ __forceinline__ void cpa16(uint32_t s, const void* g) {
    asm volatile("cp.async.cg.shared.global [%0], [%1], 16;" :: "r"(s), "l"(g));
}
#define CP_COMMIT() asm volatile("cp.async.commit_group;" ::: "memory")
#define CP_WAIT1()  asm volatile("cp.async.wait_group 1;" ::: "memory")
#define CP_WAIT0()  asm volatile("cp.async.wait_group 0;" ::: "memory")

// fp32 pair -> fp16 hi + fp16 lo words
__device__ __forceinline__ void packhl(float x, float y, uint32_t& h, uint32_t& l) {
    half2 hh = __floats2half2_rn(x, y);
    float2 hf = __half22float2(hh);
    half2 ll = __floats2half2_rn(x - hf.x, y - hf.y);
    h = *reinterpret_cast<uint32_t*>(&hh);
    l = *reinterpret_cast<uint32_t*>(&ll);
}
__device__ __forceinline__ uint32_t pack1(float x, float y) {
    half2 hh = __floats2half2_rn(x, y);
    return *reinterpret_cast<uint32_t*>(&hh);
}

// ---------------- fp32 -> fp16 hi/lo split (x) -------------------------------
__global__ void split_kernel(const float* __restrict__ src, half* __restrict__ hi,
                             half* __restrict__ lo, int n) {
    int i = (blockIdx.x * blockDim.x + threadIdx.x) * 4;
    if (i >= n) return;
    float4 v = *(const float4*)(src + i);
    uint32_t h0, l0, h1, l1;
    packhl(v.x, v.y, h0, l0);
    packhl(v.z, v.w, h1, l1);
    *(uint32_t*)(hi + i)     = h0; *(uint32_t*)(hi + i + 2) = h1;
    *(uint32_t*)(lo + i)     = l0; *(uint32_t*)(lo + i + 2) = l1;
}

// ---------------- fp32 -> fp16 convert (4 weights, one launch) ---------------
__global__ void cvtw_kernel(const float* __restrict__ w0, const float* __restrict__ w1,
                            const float* __restrict__ w2, const float* __restrict__ w3,
                            half* __restrict__ o0, half* __restrict__ o1,
                            half* __restrict__ o2, half* __restrict__ o3) {
    const int y = blockIdx.y;
    const float* s = (y == 0) ? w0 : (y == 1) ? w1 : (y == 2) ? w2 : w3;
    half* d = (y == 0) ? o0 : (y == 1) ? o1 : (y == 2) ? o2 : o3;
    int i = (blockIdx.x * blockDim.x + threadIdx.x) * 4;
    float4 v = *(const float4*)(s + i);
    *(uint32_t*)(d + i)     = pack1(v.x, v.y);
    *(uint32_t*)(d + i + 2) = pack1(v.z, v.w);
}

// ---------------- RoPE tables ------------------------------------------------
__global__ void rope_table_kernel() {
    int idx = blockIdx.x * blockDim.x + threadIdx.x;   // 2048*32
    int p   = idx & 31;
    int pos = idx >> 5;
    double freq = pow(10000.0, -(double)(2 * p) / 64.0);
    double ang  = (double)pos * freq;
    g_cos[idx] = (float)cos(ang);
    g_sin[idx] = (float)sin(ang);
}

// ---------------- HMMA fp16x2 GEMM, cp.async 3-stage, warp tile 64x64 --------
// C[m][n] = sum_k A[m][k]*B[n][k].  A = Ah+Al (fp16 split); B plain fp16.
// CTA tile: 128(M) x 256(N) x 32(K).  8 warps as 2(M) x 4(N).
// qkv=1: grid.z selects {0:Q(RoPE,x0.125,hi/lo) 1:K(RoPE) 2:V}; qkv=0: fp32 out.
#define G_RS     80                 // smem row stride bytes (32 fp16 + pad)
#define G_AH     0
#define G_AL     10240              // 128*80
#define G_B      20480
#define G_STAGE  40960              // + 256*80
#define G_NSTAGE 3

__global__ __launch_bounds__(256, 1)
void gemm_mma(const half* __restrict__ Ah, const half* __restrict__ Al,
              const half* __restrict__ B0, const half* __restrict__ B1,
              const half* __restrict__ B2,
              float* __restrict__ Cf, half* __restrict__ Qh, half* __restrict__ Ql,
              half* __restrict__ Kh, half* __restrict__ Vh,
              const int* __restrict__ tp, int qkv)
{
    extern __shared__ char sm[];
    const uint32_t smb = (uint32_t)__cvta_generic_to_shared(sm);
    const int tid = threadIdx.x, lane = tid & 31, wid = tid >> 5;
    const int wm = wid & 1, wn = wid >> 1;           // 2 x 4 warps
    const int m0 = blockIdx.y * 128, n0 = blockIdx.x * 256;
    const int z  = blockIdx.z;
    const half* W = qkv ? ((z == 0) ? B0 : (z == 1) ? B1 : B2) : B0;
    const int mode = qkv ? ((z == 0) ? 2 : (z == 1) ? 3 : 1) : 0;

    // loader mappings
    const int ar  = tid >> 1, ac = (tid & 1) * 32;            // A: 2 thr/row, 32B each
    const int br0 = tid >> 2, bc = (tid & 3) * 16;            // B: 4 thr/row, 16B each
    const char* gAh = (const char*)(Ah + (size_t)(m0 + ar) * D_MODEL) + ac;
    const char* gAl = (const char*)(Al + (size_t)(m0 + ar) * D_MODEL) + ac;
    const char* gB  = (const char*)(W  + (size_t)(n0 + br0) * D_MODEL) + bc;
    const uint32_t sAh = smb + G_AH + ar * G_RS + ac;
    const uint32_t sB  = smb + G_B  + br0 * G_RS + bc;

#define ISSUE(KT_, ST_) do { \
        const uint32_t so = (uint32_t)(ST_) * G_STAGE; \
        const int go = (KT_) * 64; \
        cpa16(so + sAh,           gAh + go); \
        cpa16(so + sAh + 16,      gAh + go + 16); \
        cpa16(so + sAh + G_AL,      gAl + go); \
        cpa16(so + sAh + G_AL + 16, gAl + go + 16); \
        _Pragma("unroll") \
        for (int p_ = 0; p_ < 4; p_++) \
            cpa16(so + sB + p_ * 64 * G_RS, gB + (size_t)p_ * 64 * D_MODEL * 2 + go); \
        CP_COMMIT(); \
    } while (0)

    float acc[4][8][4];
#pragma unroll
    for (int i = 0; i < 4; i++)
#pragma unroll
        for (int j = 0; j < 8; j++)
#pragma unroll
            for (int k = 0; k < 4; k++) acc[i][j][k] = 0.f;

    ISSUE(0, 0);
    ISSUE(1, 1);

    const int KT = D_MODEL / 32;   // 32
    for (int kt = 0; kt < KT; kt++) {
        if (kt + 1 < KT) CP_WAIT1(); else CP_WAIT0();
        __syncthreads();
        if (kt + 2 < KT) ISSUE(kt + 2, (kt + 2) % G_NSTAGE);

        const uint32_t stb = smb + (kt % G_NSTAGE) * G_STAGE;
#pragma unroll
        for (int kk = 0; kk < 2; kk++) {
            uint32_t ah[4][4], al[4][4], bh[4][4];
#pragma unroll
            for (int mi = 0; mi < 4; mi++) {
                uint32_t a = stb + (wm * 64 + mi * 16 + (lane & 15)) * G_RS
                           + kk * 32 + (lane >> 4) * 16;
                ldsm4(ah[mi], a);
                ldsm4(al[mi], a + G_AL);
            }
#pragma unroll
            for (int L = 0; L < 4; L++) {
                uint32_t a = stb + G_B
                           + (wn * 64 + L * 16 + (lane & 7) + ((lane >> 4) & 1) * 8) * G_RS
                           + kk * 32 + ((lane >> 3) & 1) * 16;
                ldsm4(bh[L], a);
            }
#pragma unroll
            for (int mi = 0; mi < 4; mi++)
#pragma unroll
                for (int nf = 0; nf < 8; nf++) {
                    const uint32_t* bp = &bh[nf >> 1][(nf & 1) * 2];
                    mma16816(acc[mi][nf], ah[mi], bp);
                    mma16816(acc[mi][nf], al[mi], bp);
                }
        }
        __syncthreads();
    }

    // epilogue
#pragma unroll
    for (int mi = 0; mi < 4; mi++)
#pragma unroll
        for (int nf = 0; nf < 8; nf++) {
            const int row0 = m0 + wm * 64 + mi * 16 + (lane >> 2);
            const int col  = n0 + wn * 64 + nf * 8 + 2 * (lane & 3);
            float v0 = acc[mi][nf][0], v1 = acc[mi][nf][1];
            float v2 = acc[mi][nf][2], v3 = acc[mi][nf][3];
            if (mode >= 2) {  // RoPE
                const int p = (col & 63) >> 1;
                const int pos0 = tp[row0 & (SEQ - 1)];
                const int pos1 = tp[(row0 + 8) & (SEQ - 1)];
                const float c0 = g_cos[pos0 * 32 + p], s0 = g_sin[pos0 * 32 + p];
                const float c1 = g_cos[pos1 * 32 + p], s1 = g_sin[pos1 * 32 + p];
                float e0 = v0 * c0 - v1 * s0, o0 = v1 * c0 + v0 * s0;
                float e1 = v2 * c1 - v3 * s1, o1 = v3 * c1 + v2 * s1;
                v0 = e0; v1 = o0; v2 = e1; v3 = o1;
                if (mode == 2) { v0 *= 0.125f; v1 *= 0.125f; v2 *= 0.125f; v3 *= 0.125f; }
            }
            if (mode == 0) {
                *(float2*)(Cf + (size_t)row0 * D_MODEL + col)       = make_float2(v0, v1);
                *(float2*)(Cf + (size_t)(row0 + 8) * D_MODEL + col) = make_float2(v2, v3);
            } else {
                const int hh = col >> 6, d = col & 63;
                const int bb = row0 >> 11, ss = row0 & (SEQ - 1);
                size_t i0 = ((size_t)(bb * N_HEADS + hh) * SEQ + ss) * D_KV + d;
                size_t i1 = i0 + 8 * D_KV;
                if (mode == 2) {
                    uint32_t h0, l0, h1, l1;
                    packhl(v0, v1, h0, l0);
                    packhl(v2, v3, h1, l1);
                    *(uint32_t*)(Qh + i0) = h0; *(uint32_t*)(Ql + i0) = l0;
                    *(uint32_t*)(Qh + i1) = h1; *(uint32_t*)(Ql + i1) = l1;
                } else if (mode == 3) {
                    *(uint32_t*)(Kh + i0) = pack1(v0, v1);
                    *(uint32_t*)(Kh + i1) = pack1(v2, v3);
                } else {
                    *(uint32_t*)(Vh + i0) = pack1(v0, v1);
                    *(uint32_t*)(Vh + i1) = pack1(v2, v3);
                }
            }
        }
#undef ISSUE
}

// ---------------- tensor-core flash attention (causal, shifted-exp softmax) --
// block 256 thr = 8 warps, each warp 16 q-rows; key tiles of 64.
#define A_RS    144                 // 64 fp16 + pad
#define A_KT    (64*A_RS)           // 9216
#define A_STAGE (2*A_KT)            // 18432 (Kh, Vh)
#define QL_OFF  18432               // Q lo tile offset (128*144)
#define ST_OFF  36864               // KV stages start

__global__ __launch_bounds__(256, 1)
void attn_mma(const half* __restrict__ Qh_, const half* __restrict__ Ql_,
              const half* __restrict__ Kh_, const half* __restrict__ Vh_,
              half* __restrict__ Oh_, half* __restrict__ Ol_)
{
    extern __shared__ char sm[];
    const uint32_t smb = (uint32_t)__cvta_generic_to_shared(sm);
    const int tid = threadIdx.x, lane = tid & 31, wid = tid >> 5;
    const int qt = gridDim.x - 1 - blockIdx.x;      // heavy blocks first
    const int q0 = qt * 128;
    const int h = blockIdx.y, b = blockIdx.z;
    const size_t hb = (size_t)(b * N_HEADS + h) * SEQ * D_KV;
    const int nt = 2 * qt + 2;

    const half* Qh = Qh_ + hb; const half* Ql = Ql_ + hb;
    const half* Kh = Kh_ + hb; const half* Vh = Vh_ + hb;

    // load Q tile (hi+lo)
    {
        const int r = tid >> 1;
        const char* gqh = (const char*)(Qh + (size_t)(q0 + r) * D_KV);
        const char* gql = (const char*)(Ql + (size_t)(q0 + r) * D_KV);
        char* sq = sm + r * A_RS;
#pragma unroll
        for (int i = 0; i < 4; i++) {
            const int c = (tid & 1) * 64 + i * 16;
            *(uint4*)(sq + c)          = *(const uint4*)(gqh + c);
            *(uint4*)(sq + QL_OFF + c) = *(const uint4*)(gql + c);
        }
    }

    // KV loader mapping: 4 threads per row, 32B each (row = 128B)
    const int kr = tid >> 2;
    const int kc = (tid & 3) * 32;
    uint4 kbuf[2][2];
#define KV_LOAD(KT_) do { \
        const size_t roff = (size_t)((KT_) * 64 + kr) * D_KV; \
        const char* t0 = (const char*)(Kh + roff); \
        const char* t1 = (const char*)(Vh + roff); \
        kbuf[0][0] = *(const uint4*)(t0 + kc); kbuf[0][1] = *(const uint4*)(t0 + kc + 16); \
        kbuf[1][0] = *(const uint4*)(t1 + kc); kbuf[1][1] = *(const uint4*)(t1 + kc + 16); \
    } while (0)
#define KV_STORE(ST_) do { \
        char* dst = sm + ST_OFF + (ST_) * A_STAGE + kr * A_RS + kc; \
        *(uint4*)(dst)             = kbuf[0][0]; \
        *(uint4*)(dst + 16)        = kbuf[0][1]; \
        *(uint4*)(dst + A_KT)      = kbuf[1][0]; \
        *(uint4*)(dst + A_KT + 16) = kbuf[1][1]; \
    } while (0)

    KV_LOAD(0);
    KV_STORE(0);
    __syncthreads();

    // Q fragments
    uint32_t qh[4][4], ql[4][4];
#pragma unroll
    for (int kk = 0; kk < 4; kk++) {
        uint32_t a = smb + (wid * 16 + (lane & 15)) * A_RS + kk * 32 + (lane >> 4) * 16;
        ldsm4(qh[kk], a);
        ldsm4(ql[kk], a + QL_OFF);
    }

    float oacc[8][4];
#pragma unroll
    for (int i = 0; i < 8; i++)
#pragma unroll
        for (int j = 0; j < 4; j++) oacc[i][j] = 0.f;
    float ls0 = 0.f, ls1 = 0.f;
    const int wr0 = q0 + wid * 16;

    for (int kt = 0; kt < nt; kt++) {
        if (kt + 1 < nt) KV_LOAD(kt + 1);
        const uint32_t stb = smb + ST_OFF + (kt & 1) * A_STAGE;
        const int kbase = kt * 64;

        if (kbase <= wr0 + 15) {
            float sacc[8][4];
#pragma unroll
            for (int i = 0; i < 8; i++)
#pragma unroll
                for (int j = 0; j < 4; j++) sacc[i][j] = 0.f;

            // S = (Qh+Ql) Kh^T
#pragma unroll
            for (int kk = 0; kk < 4; kk++) {
                uint32_t kbh[4][4];
#pragma unroll
                for (int L = 0; L < 4; L++) {
                    uint32_t a = stb + (L * 16 + (lane & 7) + ((lane >> 4) & 1) * 8) * A_RS
                               + kk * 32 + ((lane >> 3) & 1) * 16;
                    ldsm4(kbh[L], a);
                }
#pragma unroll
                for (int nf = 0; nf < 8; nf++) {
                    const uint32_t* bp = &kbh[nf >> 1][(nf & 1) * 2];
                    mma16816(sacc[nf], qh[kk], bp);
                    mma16816(sacc[nf], ql[kk], bp);
                }
            }

            // mask + shifted exp (p = e^(s-6); shift cancels in normalization)
            const bool needm = (kbase + 63 > wr0);
#pragma unroll
            for (int nf = 0; nf < 8; nf++)
#pragma unroll
                for (int j = 0; j < 4; j++) {
                    float p = __expf(sacc[nf][j] - 6.0f);
                    if (needm) {
                        const int key = kbase + nf * 8 + 2 * (lane & 3) + (j & 1);
                        const int row = wr0 + (lane >> 2) + (j >> 1) * 8;
                        if (key > row) p = 0.f;
                    }
                    sacc[nf][j] = p;
                    if (j < 2) ls0 += p; else ls1 += p;
                }

            // O += (Ph+Pl) Vh
#pragma unroll
            for (int kk2 = 0; kk2 < 4; kk2++) {
                uint32_t vh[4][4];
#pragma unroll
                for (int dL = 0; dL < 4; dL++) {
                    uint32_t a = stb + A_KT
                               + (kk2 * 16 + (lane & 7) + ((lane >> 3) & 1) * 8) * A_RS
                               + dL * 32 + ((lane >> 4) & 1) * 16;
                    ldsm4t(vh[dL], a);
                }
                uint32_t ph[4], pl[4];
                packhl(sacc[2*kk2][0],   sacc[2*kk2][1],   ph[0], pl[0]);
                packhl(sacc[2*kk2][2],   sacc[2*kk2][3],   ph[1], pl[1]);
                packhl(sacc[2*kk2+1][0], sacc[2*kk2+1][1], ph[2], pl[2]);
                packhl(sacc[2*kk2+1][2], sacc[2*kk2+1][3], ph[3], pl[3]);
#pragma unroll
                for (int df = 0; df < 8; df++) {
                    const uint32_t* bp = &vh[df >> 1][(df & 1) * 2];
                    mma16816(oacc[df], ph, bp);
                    mma16816(oacc[df], pl, bp);
                }
            }
        }

        if (kt + 1 < nt) KV_STORE((kt + 1) & 1);
        __syncthreads();
    }

    // reduce row sums across quad
    ls0 += __shfl_xor_sync(0xffffffffu, ls0, 1);
    ls0 += __shfl_xor_sync(0xffffffffu, ls0, 2);
    ls1 += __shfl_xor_sync(0xffffffffu, ls1, 1);
    ls1 += __shfl_xor_sync(0xffffffffu, ls1, 2);
    const float inv0 = 1.f / ls0, inv1 = 1.f / ls1;

    const int row0 = q0 + wid * 16 + (lane >> 2);
#pragma unroll
    for (int df = 0; df < 8; df++) {
        const int d = df * 8 + 2 * (lane & 3);
        const float v0 = oacc[df][0] * inv0, v1 = oacc[df][1] * inv0;
        const float v2 = oacc[df][2] * inv1, v3 = oacc[df][3] * inv1;
        const size_t i0 = (size_t)(b * SEQ + row0) * D_MODEL + h * D_KV + d;
        const size_t i1 = i0 + (size_t)8 * D_MODEL;
        uint32_t h0, l0, h1, l1;
        packhl(v0, v1, h0, l0);
        packhl(v2, v3, h1, l1);
        *(uint32_t*)(Oh_ + i0) = h0; *(uint32_t*)(Ol_ + i0) = l0;
        *(uint32_t*)(Oh_ + i1) = h1; *(uint32_t*)(Ol_ + i1) = l1;
    }
}

// ---------------- host launcher ----------------------------------------------
extern "C" void kernel_launch(void* const* d_in, const int* in_sizes, int n_in,
                              void* d_out, int out_size)
{
    const float* x  = (const float*)d_in[0];
    const float* wq = (const float*)d_in[1];
    const float* wk = (const float*)d_in[2];
    const float* wv = (const float*)d_in[3];
    const float* wo = (const float*)d_in[4];
    const int*   tp = (const int*)d_in[5];
    float* out = (float*)d_out;

    half *xh, *xl, *wqh, *wkh, *wvh, *woh;
    half *Qh, *Ql, *Kh, *Vh, *Oh, *Ol;
    cudaGetSymbolAddress((void**)&xh, g_xh);   cudaGetSymbolAddress((void**)&xl, g_xl);
    cudaGetSymbolAddress((void**)&wqh, g_wqh); cudaGetSymbolAddress((void**)&wkh, g_wkh);
    cudaGetSymbolAddress((void**)&wvh, g_wvh); cudaGetSymbolAddress((void**)&woh, g_woh);
    cudaGetSymbolAddress((void**)&Qh, g_Qh);   cudaGetSymbolAddress((void**)&Ql, g_Ql);
    cudaGetSymbolAddress((void**)&Kh, g_Kh);   cudaGetSymbolAddress((void**)&Vh, g_Vh);
    cudaGetSymbolAddress((void**)&Oh, g_Oh);   cudaGetSymbolAddress((void**)&Ol, g_Ol);

    const int gemm_smem = G_NSTAGE * G_STAGE;                 // 122880
    const int attn_smem = ST_OFF + 2 * A_STAGE;               // 73728
    cudaFuncSetAttribute(gemm_mma, cudaFuncAttributeMaxDynamicSharedMemorySize, gemm_smem);
    cudaFuncSetAttribute(attn_mma, cudaFuncAttributeMaxDynamicSharedMemorySize, attn_smem);

    // splits / converts / tables (3 launches)
    split_kernel<<<M_TOTAL * D_MODEL / 1024, 256>>>(x, xh, xl, M_TOTAL * D_MODEL);
    cvtw_kernel<<<dim3(D_MODEL * D_MODEL / 1024, 4), 256>>>(wq, wk, wv, wo,
                                                            wqh, wkh, wvh, woh);
    rope_table_kernel<<<SEQ * 32 / 256, 256>>>();

    // fused QKV projections (one launch)
    dim3 qkvgrid(D_MODEL / 256, M_TOTAL / 128, 3);   // (4, 32, 3)
    gemm_mma<<<qkvgrid, 256, gemm_smem>>>(xh, xl, wqh, wkh, wvh,
                                          nullptr, Qh, Ql, Kh, Vh, tp, 1);

    // attention
    dim3 agrid(SEQ / 128, N_HEADS, BATCH);           // (16,16,2)
    attn_mma<<<agrid, 256, attn_smem>>>(Qh, Ql, Kh, Vh, Oh, Ol);

    // output projection
    dim3 ogrid(D_MODEL / 256, M_TOTAL / 128, 1);
    gemm_mma<<<ogrid, 256, gemm_smem>>>(Oh, Ol, woh, nullptr, nullptr,
                                        out, nullptr, nullptr, nullptr, nullptr, tp, 0);
}

// round 10
// speedup vs baseline: 4.0914x; 1.0108x over previous
#include <cuda_runtime.h>
#include <cuda_fp16.h>
#include <math.h>
#include <cstdint>

#define D_MODEL 1024
#define N_HEADS 16
#define D_KV    64
#define BATCH   2
#define SEQ     2048
#define M_TOTAL (BATCH*SEQ)     // 4096

// ---------------- scratch (device globals) ----------------------------------
__device__ half g_xh[(size_t)M_TOTAL*D_MODEL],  g_xl[(size_t)M_TOTAL*D_MODEL];
__device__ half g_wqh[(size_t)D_MODEL*D_MODEL];
__device__ half g_wkh[(size_t)D_MODEL*D_MODEL];
__device__ half g_wvh[(size_t)D_MODEL*D_MODEL];
__device__ half g_woh[(size_t)D_MODEL*D_MODEL];
__device__ half g_Qh[(size_t)M_TOTAL*D_MODEL],  g_Ql[(size_t)M_TOTAL*D_MODEL]; // [b,h,s,d]
__device__ half g_Kh[(size_t)M_TOTAL*D_MODEL];                                  // [b,h,s,d]
__device__ half g_Vh[(size_t)M_TOTAL*D_MODEL];
__device__ half g_Oh[(size_t)M_TOTAL*D_MODEL],  g_Ol[(size_t)M_TOTAL*D_MODEL]; // [b*s, h*64+d]
__device__ float g_cos[SEQ*(D_KV/2)];
__device__ float g_sin[SEQ*(D_KV/2)];

// ---------------- mma / ldmatrix / cp.async helpers --------------------------
__device__ __forceinline__ void ldsm4(uint32_t* r, uint32_t a) {
    asm volatile("ldmatrix.sync.aligned.m8n8.x4.shared.b16 {%0,%1,%2,%3}, [%4];"
        : "=r"(r[0]), "=r"(r[1]), "=r"(r[2]), "=r"(r[3]) : "r"(a));
}
__device__ __forceinline__ void ldsm4t(uint32_t* r, uint32_t a) {
    asm volatile("ldmatrix.sync.aligned.m8n8.x4.trans.shared.b16 {%0,%1,%2,%3}, [%4];"
        : "=r"(r[0]), "=r"(r[1]), "=r"(r[2]), "=r"(r[3]) : "r"(a));
}
__device__ __forceinline__ void mma16816(float* c, const uint32_t* a, const uint32_t* b) {
    asm volatile("mma.sync.aligned.m16n8k16.row.col.f32.f16.f16.f32 "
        "{%0,%1,%2,%3}, {%4,%5,%6,%7}, {%8,%9}, {%0,%1,%2,%3};"
        : "+f"(c[0]), "+f"(c[1]), "+f"(c[2]), "+f"(c[3])
        : "r"(a[0]), "r"(a[1]), "r"(a[2]), "r"(a[3]), "r"(b[0]), "r"(b[1]));
}
__device__ __forceinline__ void cpa16(uint32_t s, const void* g) {
    asm volatile("cp.async.cg.shared.global [%0], [%1], 16;" :: "r"(s), "l"(g));
}
#define CP_COMMIT() asm volatile("cp.async.commit_group;" ::: "memory")
#define CP_WAIT1()  asm volatile("cp.async.wait_group 1;" ::: "memory")
#define CP_WAIT0()  asm volatile("cp.async.wait_group 0;" ::: "memory")

// fp32 pair -> fp16 hi + fp16 lo words
__device__ __forceinline__ void packhl(float x, float y, uint32_t& h, uint32_t& l) {
    half2 hh = __floats2half2_rn(x, y);
    float2 hf = __half22float2(hh);
    half2 ll = __floats2half2_rn(x - hf.x, y - hf.y);
    h = *reinterpret_cast<uint32_t*>(&hh);
    l = *reinterpret_cast<uint32_t*>(&ll);
}
__device__ __forceinline__ uint32_t pack1(float x, float y) {
    half2 hh = __floats2half2_rn(x, y);
    return *reinterpret_cast<uint32_t*>(&hh);
}

// ---------------- fp32 -> fp16 hi/lo split (x) -------------------------------
__global__ void split_kernel(const float* __restrict__ src, half* __restrict__ hi,
                             half* __restrict__ lo, int n) {
    int i = (blockIdx.x * blockDim.x + threadIdx.x) * 4;
    if (i >= n) return;
    float4 v = *(const float4*)(src + i);
    uint32_t h0, l0, h1, l1;
    packhl(v.x, v.y, h0, l0);
    packhl(v.z, v.w, h1, l1);
    *(uint32_t*)(hi + i)     = h0; *(uint32_t*)(hi + i + 2) = h1;
    *(uint32_t*)(lo + i)     = l0; *(uint32_t*)(lo + i + 2) = l1;
}

// ---------------- fp32 -> fp16 convert (4 weights, one launch) ---------------
__global__ void cvtw_kernel(const float* __restrict__ w0, const float* __restrict__ w1,
                            const float* __restrict__ w2, const float* __restrict__ w3,
                            half* __restrict__ o0, half* __restrict__ o1,
                            half* __restrict__ o2, half* __restrict__ o3) {
    const int y = blockIdx.y;
    const float* s = (y == 0) ? w0 : (y == 1) ? w1 : (y == 2) ? w2 : w3;
    half* d = (y == 0) ? o0 : (y == 1) ? o1 : (y == 2) ? o2 : o3;
    int i = (blockIdx.x * blockDim.x + threadIdx.x) * 4;
    float4 v = *(const float4*)(s + i);
    *(uint32_t*)(d + i)     = pack1(v.x, v.y);
    *(uint32_t*)(d + i + 2) = pack1(v.z, v.w);
}

// ---------------- RoPE tables ------------------------------------------------
__global__ void rope_table_kernel() {
    int idx = blockIdx.x * blockDim.x + threadIdx.x;   // 2048*32
    int p   = idx & 31;
    int pos = idx >> 5;
    double freq = pow(10000.0, -(double)(2 * p) / 64.0);
    double ang  = (double)pos * freq;
    g_cos[idx] = (float)cos(ang);
    g_sin[idx] = (float)sin(ang);
}

// ---------------- HMMA fp16x2 GEMM, cp.async 3-stage, warp tile 64x64 --------
// C[m][n] = sum_k A[m][k]*B[n][k].  A = Ah+Al (fp16 split); B plain fp16.
// CTA tile: 128(M) x 256(N) x 32(K).  8 warps as 2(M) x 4(N).
// hi-term sweep then lo-term sweep: dependent MMAs 32 apart.
#define G_RS     80                 // smem row stride bytes (32 fp16 + pad)
#define G_AH     0
#define G_AL     10240              // 128*80
#define G_B      20480
#define G_STAGE  40960              // + 256*80
#define G_NSTAGE 3

__global__ __launch_bounds__(256, 1)
void gemm_mma(const half* __restrict__ Ah, const half* __restrict__ Al,
              const half* __restrict__ B0, const half* __restrict__ B1,
              const half* __restrict__ B2,
              float* __restrict__ Cf, half* __restrict__ Qh, half* __restrict__ Ql,
              half* __restrict__ Kh, half* __restrict__ Vh,
              const int* __restrict__ tp, int qkv)
{
    extern __shared__ char sm[];
    const uint32_t smb = (uint32_t)__cvta_generic_to_shared(sm);
    const int tid = threadIdx.x, lane = tid & 31, wid = tid >> 5;
    const int wm = wid & 1, wn = wid >> 1;           // 2 x 4 warps
    const int m0 = blockIdx.y * 128, n0 = blockIdx.x * 256;
    const int z  = blockIdx.z;
    const half* W = qkv ? ((z == 0) ? B0 : (z == 1) ? B1 : B2) : B0;
    const int mode = qkv ? ((z == 0) ? 2 : (z == 1) ? 3 : 1) : 0;

    // loader mappings
    const int ar  = tid >> 1, ac = (tid & 1) * 32;            // A: 2 thr/row, 32B each
    const int br0 = tid >> 2, bc = (tid & 3) * 16;            // B: 4 thr/row, 16B each
    const char* gAh = (const char*)(Ah + (size_t)(m0 + ar) * D_MODEL) + ac;
    const char* gAl = (const char*)(Al + (size_t)(m0 + ar) * D_MODEL) + ac;
    const char* gB  = (const char*)(W  + (size_t)(n0 + br0) * D_MODEL) + bc;
    const uint32_t sAh = smb + G_AH + ar * G_RS + ac;
    const uint32_t sB  = smb + G_B  + br0 * G_RS + bc;

#define ISSUE(KT_, ST_) do { \
        const uint32_t so = (uint32_t)(ST_) * G_STAGE; \
        const int go = (KT_) * 64; \
        cpa16(so + sAh,           gAh + go); \
        cpa16(so + sAh + 16,      gAh + go + 16); \
        cpa16(so + sAh + G_AL,      gAl + go); \
        cpa16(so + sAh + G_AL + 16, gAl + go + 16); \
        _Pragma("unroll") \
        for (int p_ = 0; p_ < 4; p_++) \
            cpa16(so + sB + p_ * 64 * G_RS, gB + (size_t)p_ * 64 * D_MODEL * 2 + go); \
        CP_COMMIT(); \
    } while (0)

    float acc[4][8][4];
#pragma unroll
    for (int i = 0; i < 4; i++)
#pragma unroll
        for (int j = 0; j < 8; j++)
#pragma unroll
            for (int k = 0; k < 4; k++) acc[i][j][k] = 0.f;

    ISSUE(0, 0);
    ISSUE(1, 1);

    const int KT = D_MODEL / 32;   // 32
    for (int kt = 0; kt < KT; kt++) {
        if (kt + 1 < KT) CP_WAIT1(); else CP_WAIT0();
        __syncthreads();
        // safe with 3 stages + <=1-iter warp skew: stage (kt+2)%3 != kt%3,(kt+1)%3
        if (kt + 2 < KT) ISSUE(kt + 2, (kt + 2) % G_NSTAGE);

        const uint32_t stb = smb + (kt % G_NSTAGE) * G_STAGE;
#pragma unroll
        for (int kk = 0; kk < 2; kk++) {
            uint32_t ah[4][4], al[4][4], bh[4][4];
#pragma unroll
            for (int mi = 0; mi < 4; mi++) {
                uint32_t a = stb + (wm * 64 + mi * 16 + (lane & 15)) * G_RS
                           + kk * 32 + (lane >> 4) * 16;
                ldsm4(ah[mi], a);
                ldsm4(al[mi], a + G_AL);
            }
#pragma unroll
            for (int L = 0; L < 4; L++) {
                uint32_t a = stb + G_B
                           + (wn * 64 + L * 16 + (lane & 7) + ((lane >> 4) & 1) * 8) * G_RS
                           + kk * 32 + ((lane >> 3) & 1) * 16;
                ldsm4(bh[L], a);
            }
            // hi sweep (32 independent MMAs), then lo sweep
#pragma unroll
            for (int mi = 0; mi < 4; mi++)
#pragma unroll
                for (int nf = 0; nf < 8; nf++)
                    mma16816(acc[mi][nf], ah[mi], &bh[nf >> 1][(nf & 1) * 2]);
#pragma unroll
            for (int mi = 0; mi < 4; mi++)
#pragma unroll
                for (int nf = 0; nf < 8; nf++)
                    mma16816(acc[mi][nf], al[mi], &bh[nf >> 1][(nf & 1) * 2]);
        }
    }

    // epilogue
#pragma unroll
    for (int mi = 0; mi < 4; mi++)
#pragma unroll
        for (int nf = 0; nf < 8; nf++) {
            const int row0 = m0 + wm * 64 + mi * 16 + (lane >> 2);
            const int col  = n0 + wn * 64 + nf * 8 + 2 * (lane & 3);
            float v0 = acc[mi][nf][0], v1 = acc[mi][nf][1];
            float v2 = acc[mi][nf][2], v3 = acc[mi][nf][3];
            if (mode >= 2) {  // RoPE
                const int p = (col & 63) >> 1;
                const int pos0 = tp[row0 & (SEQ - 1)];
                const int pos1 = tp[(row0 + 8) & (SEQ - 1)];
                const float c0 = g_cos[pos0 * 32 + p], s0 = g_sin[pos0 * 32 + p];
                const float c1 = g_cos[pos1 * 32 + p], s1 = g_sin[pos1 * 32 + p];
                float e0 = v0 * c0 - v1 * s0, o0 = v1 * c0 + v0 * s0;
                float e1 = v2 * c1 - v3 * s1, o1 = v3 * c1 + v2 * s1;
                v0 = e0; v1 = o0; v2 = e1; v3 = o1;
                if (mode == 2) { v0 *= 0.125f; v1 *= 0.125f; v2 *= 0.125f; v3 *= 0.125f; }
            }
            if (mode == 0) {
                *(float2*)(Cf + (size_t)row0 * D_MODEL + col)       = make_float2(v0, v1);
                *(float2*)(Cf + (size_t)(row0 + 8) * D_MODEL + col) = make_float2(v2, v3);
            } else {
                const int hh = col >> 6, d = col & 63;
                const int bb = row0 >> 11, ss = row0 & (SEQ - 1);
                size_t i0 = ((size_t)(bb * N_HEADS + hh) * SEQ + ss) * D_KV + d;
                size_t i1 = i0 + 8 * D_KV;
                if (mode == 2) {
                    uint32_t h0, l0, h1, l1;
                    packhl(v0, v1, h0, l0);
                    packhl(v2, v3, h1, l1);
                    *(uint32_t*)(Qh + i0) = h0; *(uint32_t*)(Ql + i0) = l0;
                    *(uint32_t*)(Qh + i1) = h1; *(uint32_t*)(Ql + i1) = l1;
                } else if (mode == 3) {
                    *(uint32_t*)(Kh + i0) = pack1(v0, v1);
                    *(uint32_t*)(Kh + i1) = pack1(v2, v3);
                } else {
                    *(uint32_t*)(Vh + i0) = pack1(v0, v1);
                    *(uint32_t*)(Vh + i1) = pack1(v2, v3);
                }
            }
        }
#undef ISSUE
}

// ---------------- tensor-core flash attention (causal, shifted-exp softmax) --
// block 256 thr = 8 warps, each warp 16 q-rows; key tiles of 64.
#define A_RS    144                 // 64 fp16 + pad
#define A_KT    (64*A_RS)           // 9216
#define A_STAGE (2*A_KT)            // 18432 (Kh, Vh)
#define QL_OFF  18432               // Q lo tile offset (128*144)
#define ST_OFF  36864               // KV stages start

__global__ __launch_bounds__(256, 1)
void attn_mma(const half* __restrict__ Qh_, const half* __restrict__ Ql_,
              const half* __restrict__ Kh_, const half* __restrict__ Vh_,
              half* __restrict__ Oh_, half* __restrict__ Ol_)
{
    extern __shared__ char sm[];
    const uint32_t smb = (uint32_t)__cvta_generic_to_shared(sm);
    const int tid = threadIdx.x, lane = tid & 31, wid = tid >> 5;
    const int qt = gridDim.x - 1 - blockIdx.x;      // heavy blocks first
    const int q0 = qt * 128;
    const int h = blockIdx.y, b = blockIdx.z;
    const size_t hb = (size_t)(b * N_HEADS + h) * SEQ * D_KV;
    const int nt = 2 * qt + 2;

    const half* Qh = Qh_ + hb; const half* Ql = Ql_ + hb;
    const half* Kh = Kh_ + hb; const half* Vh = Vh_ + hb;

    // load Q tile (hi+lo)
    {
        const int r = tid >> 1;
        const char* gqh = (const char*)(Qh + (size_t)(q0 + r) * D_KV);
        const char* gql = (const char*)(Ql + (size_t)(q0 + r) * D_KV);
        char* sq = sm + r * A_RS;
#pragma unroll
        for (int i = 0; i < 4; i++) {
            const int c = (tid & 1) * 64 + i * 16;
            *(uint4*)(sq + c)          = *(const uint4*)(gqh + c);
            *(uint4*)(sq + QL_OFF + c) = *(const uint4*)(gql + c);
        }
    }

    // KV loader mapping: 4 threads per row, 32B each (row = 128B)
    const int kr = tid >> 2;
    const int kc = (tid & 3) * 32;
    uint4 kbuf[2][2];
#define KV_LOAD(KT_) do { \
        const size_t roff = (size_t)((KT_) * 64 + kr) * D_KV; \
        const char* t0 = (const char*)(Kh + roff); \
        const char* t1 = (const char*)(Vh + roff); \
        kbuf[0][0] = *(const uint4*)(t0 + kc); kbuf[0][1] = *(const uint4*)(t0 + kc + 16); \
        kbuf[1][0] = *(const uint4*)(t1 + kc); kbuf[1][1] = *(const uint4*)(t1 + kc + 16); \
    } while (0)
#define KV_STORE(ST_) do { \
        char* dst = sm + ST_OFF + (ST_) * A_STAGE + kr * A_RS + kc; \
        *(uint4*)(dst)             = kbuf[0][0]; \
        *(uint4*)(dst + 16)        = kbuf[0][1]; \
        *(uint4*)(dst + A_KT)      = kbuf[1][0]; \
        *(uint4*)(dst + A_KT + 16) = kbuf[1][1]; \
    } while (0)

    KV_LOAD(0);
    KV_STORE(0);
    __syncthreads();

    // Q fragments
    uint32_t qh[4][4], ql[4][4];
#pragma unroll
    for (int kk = 0; kk < 4; kk++) {
        uint32_t a = smb + (wid * 16 + (lane & 15)) * A_RS + kk * 32 + (lane >> 4) * 16;
        ldsm4(qh[kk], a);
        ldsm4(ql[kk], a + QL_OFF);
    }

    float oacc[8][4];
#pragma unroll
    for (int i = 0; i < 8; i++)
#pragma unroll
        for (int j = 0; j < 4; j++) oacc[i][j] = 0.f;
    float ls0 = 0.f, ls1 = 0.f;
    const int wr0 = q0 + wid * 16;

    for (int kt = 0; kt < nt; kt++) {
        if (kt + 1 < nt) KV_LOAD(kt + 1);
        const uint32_t stb = smb + ST_OFF + (kt & 1) * A_STAGE;
        const int kbase = kt * 64;

        if (kbase <= wr0 + 15) {
            float sacc[8][4];
#pragma unroll
            for (int i = 0; i < 8; i++)
#pragma unroll
                for (int j = 0; j < 4; j++) sacc[i][j] = 0.f;

            // S = (Qh+Ql) Kh^T  -- hi sweep then lo sweep per kk
#pragma unroll
            for (int kk = 0; kk < 4; kk++) {
                uint32_t kbh[4][4];
#pragma unroll
                for (int L = 0; L < 4; L++) {
                    uint32_t a = stb + (L * 16 + (lane & 7) + ((lane >> 4) & 1) * 8) * A_RS
                               + kk * 32 + ((lane >> 3) & 1) * 16;
                    ldsm4(kbh[L], a);
                }
#pragma unroll
                for (int nf = 0; nf < 8; nf++)
                    mma16816(sacc[nf], qh[kk], &kbh[nf >> 1][(nf & 1) * 2]);
#pragma unroll
                for (int nf = 0; nf < 8; nf++)
                    mma16816(sacc[nf], ql[kk], &kbh[nf >> 1][(nf & 1) * 2]);
            }

            // mask + shifted exp (p = e^(s-6); shift cancels in normalization)
            const bool needm = (kbase + 63 > wr0);
#pragma unroll
            for (int nf = 0; nf < 8; nf++)
#pragma unroll
                for (int j = 0; j < 4; j++) {
                    float p = __expf(sacc[nf][j] - 6.0f);
                    if (needm) {
                        const int key = kbase + nf * 8 + 2 * (lane & 3) + (j & 1);
                        const int row = wr0 + (lane >> 2) + (j >> 1) * 8;
                        if (key > row) p = 0.f;
                    }
                    sacc[nf][j] = p;
                    if (j < 2) ls0 += p; else ls1 += p;
                }

            // O += (Ph+Pl) Vh  -- hi sweep then lo sweep per kk2
#pragma unroll
            for (int kk2 = 0; kk2 < 4; kk2++) {
                uint32_t vh[4][4];
#pragma unroll
                for (int dL = 0; dL < 4; dL++) {
                    uint32_t a = stb + A_KT
                               + (kk2 * 16 + (lane & 7) + ((lane >> 3) & 1) * 8) * A_RS
                               + dL * 32 + ((lane >> 4) & 1) * 16;
                    ldsm4t(vh[dL], a);
                }
                uint32_t ph[4], pl[4];
                packhl(sacc[2*kk2][0],   sacc[2*kk2][1],   ph[0], pl[0]);
                packhl(sacc[2*kk2][2],   sacc[2*kk2][3],   ph[1], pl[1]);
                packhl(sacc[2*kk2+1][0], sacc[2*kk2+1][1], ph[2], pl[2]);
                packhl(sacc[2*kk2+1][2], sacc[2*kk2+1][3], ph[3], pl[3]);
#pragma unroll
                for (int df = 0; df < 8; df++)
                    mma16816(oacc[df], ph, &vh[df >> 1][(df & 1) * 2]);
#pragma unroll
                for (int df = 0; df < 8; df++)
                    mma16816(oacc[df], pl, &vh[df >> 1][(df & 1) * 2]);
            }
        }

        if (kt + 1 < nt) KV_STORE((kt + 1) & 1);
        __syncthreads();
    }

    // reduce row sums across quad
    ls0 += __shfl_xor_sync(0xffffffffu, ls0, 1);
    ls0 += __shfl_xor_sync(0xffffffffu, ls0, 2);
    ls1 += __shfl_xor_sync(0xffffffffu, ls1, 1);
    ls1 += __shfl_xor_sync(0xffffffffu, ls1, 2);
    const float inv0 = 1.f / ls0, inv1 = 1.f / ls1;

    const int row0 = q0 + wid * 16 + (lane >> 2);
#pragma unroll
    for (int df = 0; df < 8; df++) {
        const int d = df * 8 + 2 * (lane & 3);
        const float v0 = oacc[df][0] * inv0, v1 = oacc[df][1] * inv0;
        const float v2 = oacc[df][2] * inv1, v3 = oacc[df][3] * inv1;
        const size_t i0 = (size_t)(b * SEQ + row0) * D_MODEL + h * D_KV + d;
        const size_t i1 = i0 + (size_t)8 * D_MODEL;
        uint32_t h0, l0, h1, l1;
        packhl(v0, v1, h0, l0);
        packhl(v2, v3, h1, l1);
        *(uint32_t*)(Oh_ + i0) = h0; *(uint32_t*)(Ol_ + i0) = l0;
        *(uint32_t*)(Oh_ + i1) = h1; *(uint32_t*)(Ol_ + i1) = l1;
    }
}

// ---------------- host launcher ----------------------------------------------
extern "C" void kernel_launch(void* const* d_in, const int* in_sizes, int n_in,
                              void* d_out, int out_size)
{
    const float* x  = (const float*)d_in[0];
    const float* wq = (const float*)d_in[1];
    const float* wk = (const float*)d_in[2];
    const float* wv = (const float*)d_in[3];
    const float* wo = (const float*)d_in[4];
    const int*   tp = (const int*)d_in[5];
    float* out = (float*)d_out;

    half *xh, *xl, *wqh, *wkh, *wvh, *woh;
    half *Qh, *Ql, *Kh, *Vh, *Oh, *Ol;
    cudaGetSymbolAddress((void**)&xh, g_xh);   cudaGetSymbolAddress((void**)&xl, g_xl);
    cudaGetSymbolAddress((void**)&wqh, g_wqh); cudaGetSymbolAddress((void**)&wkh, g_wkh);
    cudaGetSymbolAddress((void**)&wvh, g_wvh); cudaGetSymbolAddress((void**)&woh, g_woh);
    cudaGetSymbolAddress((void**)&Qh, g_Qh);   cudaGetSymbolAddress((void**)&Ql, g_Ql);
    cudaGetSymbolAddress((void**)&Kh, g_Kh);   cudaGetSymbolAddress((void**)&Vh, g_Vh);
    cudaGetSymbolAddress((void**)&Oh, g_Oh);   cudaGetSymbolAddress((void**)&Ol, g_Ol);

    const int gemm_smem = G_NSTAGE * G_STAGE;                 // 122880
    const int attn_smem = ST_OFF + 2 * A_STAGE;               // 73728
    cudaFuncSetAttribute(gemm_mma, cudaFuncAttributeMaxDynamicSharedMemorySize, gemm_smem);
    cudaFuncSetAttribute(attn_mma, cudaFuncAttributeMaxDynamicSharedMemorySize, attn_smem);

    // splits / converts / tables (3 launches)
    split_kernel<<<M_TOTAL * D_MODEL / 1024, 256>>>(x, xh, xl, M_TOTAL * D_MODEL);
    cvtw_kernel<<<dim3(D_MODEL * D_MODEL / 1024, 4), 256>>>(wq, wk, wv, wo,
                                                            wqh, wkh, wvh, woh);
    rope_table_kernel<<<SEQ * 32 / 256, 256>>>();

    // fused QKV projections (one launch)
    dim3 qkvgrid(D_MODEL / 256, M_TOTAL / 128, 3);   // (4, 32, 3)
    gemm_mma<<<qkvgrid, 256, gemm_smem>>>(xh, xl, wqh, wkh, wvh,
                                          nullptr, Qh, Ql, Kh, Vh, tp, 1);

    // attention
    dim3 agrid(SEQ / 128, N_HEADS, BATCH);           // (16,16,2)
    attn_mma<<<agrid, 256, attn_smem>>>(Qh, Ql, Kh, Vh, Oh, Ol);

    // output projection
    dim3 ogrid(D_MODEL / 256, M_TOTAL / 128, 1);
    gemm_mma<<<ogrid, 256, gemm_smem>>>(Oh, Ol, woh, nullptr, nullptr,
                                        out, nullptr, nullptr, nullptr, nullptr, tp, 0);
}

// round 11
// speedup vs baseline: 4.1861x; 1.0231x over previous
#include <cuda_runtime.h>
#include <cuda_fp16.h>
#include <math.h>
#include <cstdint>

#define D_MODEL 1024
#define N_HEADS 16
#define D_KV    64
#define BATCH   2
#define SEQ     2048
#define M_TOTAL (BATCH*SEQ)     // 4096

// ---------------- scratch (device globals) ----------------------------------
__device__ half g_xh[(size_t)M_TOTAL*D_MODEL],  g_xl[(size_t)M_TOTAL*D_MODEL];
__device__ half g_wqh[(size_t)D_MODEL*D_MODEL];
__device__ half g_wkh[(size_t)D_MODEL*D_MODEL];
__device__ half g_wvh[(size_t)D_MODEL*D_MODEL];
__device__ half g_woh[(size_t)D_MODEL*D_MODEL];
__device__ half g_Qh[(size_t)M_TOTAL*D_MODEL],  g_Ql[(size_t)M_TOTAL*D_MODEL]; // [b,h,s,d]
__device__ half g_Kh[(size_t)M_TOTAL*D_MODEL];                                  // [b,h,s,d]
__device__ half g_Vh[(size_t)M_TOTAL*D_MODEL];
__device__ half g_Oh[(size_t)M_TOTAL*D_MODEL],  g_Ol[(size_t)M_TOTAL*D_MODEL]; // [b*s, h*64+d]
__device__ float g_cos[SEQ*(D_KV/2)];
__device__ float g_sin[SEQ*(D_KV/2)];

// ---------------- mma / ldmatrix / cp.async helpers --------------------------
__device__ __forceinline__ void ldsm4(uint32_t* r, uint32_t a) {
    asm volatile("ldmatrix.sync.aligned.m8n8.x4.shared.b16 {%0,%1,%2,%3}, [%4];"
        : "=r"(r[0]), "=r"(r[1]), "=r"(r[2]), "=r"(r[3]) : "r"(a));
}
__device__ __forceinline__ void ldsm4t(uint32_t* r, uint32_t a) {
    asm volatile("ldmatrix.sync.aligned.m8n8.x4.trans.shared.b16 {%0,%1,%2,%3}, [%4];"
        : "=r"(r[0]), "=r"(r[1]), "=r"(r[2]), "=r"(r[3]) : "r"(a));
}
__device__ __forceinline__ void mma16816(float* c, const uint32_t* a, const uint32_t* b) {
    asm volatile("mma.sync.aligned.m16n8k16.row.col.f32.f16.f16.f32 "
        "{%0,%1,%2,%3}, {%4,%5,%6,%7}, {%8,%9}, {%0,%1,%2,%3};"
        : "+f"(c[0]), "+f"(c[1]), "+f"(c[2]), "+f"(c[3])
        : "r"(a[0]), "r"(a[1]), "r"(a[2]), "r"(a[3]), "r"(b[0]), "r"(b[1]));
}
__device__ __forceinline__ void cpa16(uint32_t s, const void* g) {
    asm volatile("cp.async.cg.shared.global [%0], [%1], 16;" :: "r"(s), "l"(g));
}
#define CP_COMMIT() asm volatile("cp.async.commit_group;" ::: "memory")
#define CP_WAIT1()  asm volatile("cp.async.wait_group 1;" ::: "memory")
#define CP_WAIT0()  asm volatile("cp.async.wait_group 0;" ::: "memory")

// fp32 pair -> fp16 hi + fp16 lo words
__device__ __forceinline__ void packhl(float x, float y, uint32_t& h, uint32_t& l) {
    half2 hh = __floats2half2_rn(x, y);
    float2 hf = __half22float2(hh);
    half2 ll = __floats2half2_rn(x - hf.x, y - hf.y);
    h = *reinterpret_cast<uint32_t*>(&hh);
    l = *reinterpret_cast<uint32_t*>(&ll);
}
__device__ __forceinline__ uint32_t pack1(float x, float y) {
    half2 hh = __floats2half2_rn(x, y);
    return *reinterpret_cast<uint32_t*>(&hh);
}

// ---------------- fp32 -> fp16 hi/lo split (x) -------------------------------
__global__ void split_kernel(const float* __restrict__ src, half* __restrict__ hi,
                             half* __restrict__ lo, int n) {
    int i = (blockIdx.x * blockDim.x + threadIdx.x) * 4;
    if (i >= n) return;
    float4 v = *(const float4*)(src + i);
    uint32_t h0, l0, h1, l1;
    packhl(v.x, v.y, h0, l0);
    packhl(v.z, v.w, h1, l1);
    *(uint32_t*)(hi + i)     = h0; *(uint32_t*)(hi + i + 2) = h1;
    *(uint32_t*)(lo + i)     = l0; *(uint32_t*)(lo + i + 2) = l1;
}

// ---------------- fp32 -> fp16 convert (4 weights, one launch) ---------------
__global__ void cvtw_kernel(const float* __restrict__ w0, const float* __restrict__ w1,
                            const float* __restrict__ w2, const float* __restrict__ w3,
                            half* __restrict__ o0, half* __restrict__ o1,
                            half* __restrict__ o2, half* __restrict__ o3) {
    const int y = blockIdx.y;
    const float* s = (y == 0) ? w0 : (y == 1) ? w1 : (y == 2) ? w2 : w3;
    half* d = (y == 0) ? o0 : (y == 1) ? o1 : (y == 2) ? o2 : o3;
    int i = (blockIdx.x * blockDim.x + threadIdx.x) * 4;
    float4 v = *(const float4*)(s + i);
    *(uint32_t*)(d + i)     = pack1(v.x, v.y);
    *(uint32_t*)(d + i + 2) = pack1(v.z, v.w);
}

// ---------------- RoPE tables ------------------------------------------------
__global__ void rope_table_kernel() {
    int idx = blockIdx.x * blockDim.x + threadIdx.x;   // 2048*32
    int p   = idx & 31;
    int pos = idx >> 5;
    double freq = pow(10000.0, -(double)(2 * p) / 64.0);
    double ang  = (double)pos * freq;
    g_cos[idx] = (float)cos(ang);
    g_sin[idx] = (float)sin(ang);
}

// ---------------- HMMA fp16x2 GEMM, cp.async 3-stage, 512 thr ----------------
// C[m][n] = sum_k A[m][k]*B[n][k].  A = Ah+Al (fp16 split); B plain fp16.
// CTA tile: 128(M) x 256(N) x 32(K).  16 warps as 2(M) x 8(N); warp tile 64x32.
// 4 warps/SMSP for latency hiding (was 2).
#define G_RS     80                 // smem row stride bytes (32 fp16 + pad)
#define G_AH     0
#define G_AL     10240              // 128*80
#define G_B      20480
#define G_STAGE  40960              // + 256*80
#define G_NSTAGE 3

__global__ __launch_bounds__(512, 1)
void gemm_mma(const half* __restrict__ Ah, const half* __restrict__ Al,
              const half* __restrict__ B0, const half* __restrict__ B1,
              const half* __restrict__ B2,
              float* __restrict__ Cf, half* __restrict__ Qh, half* __restrict__ Ql,
              half* __restrict__ Kh, half* __restrict__ Vh,
              const int* __restrict__ tp, int qkv)
{
    extern __shared__ char sm[];
    const uint32_t smb = (uint32_t)__cvta_generic_to_shared(sm);
    const int tid = threadIdx.x, lane = tid & 31, wid = tid >> 5;
    const int wm = wid & 1, wn = wid >> 1;           // 2(M) x 8(N) warps
    const int m0 = blockIdx.y * 128, n0 = blockIdx.x * 256;
    const int z  = blockIdx.z;
    const half* W = qkv ? ((z == 0) ? B0 : (z == 1) ? B1 : B2) : B0;
    const int mode = qkv ? ((z == 0) ? 2 : (z == 1) ? 3 : 1) : 0;

    // loader mappings (512 thr, 4 cpa16 each)
    const int arow = tid >> 2, acol = (tid & 3) * 16;   // A: 4 thr/row, 16B each
    const char* gAh = (const char*)(Ah + (size_t)(m0 + arow) * D_MODEL) + acol;
    const char* gAl = (const char*)(Al + (size_t)(m0 + arow) * D_MODEL) + acol;
    const char* gB0 = (const char*)(W  + (size_t)(n0 + arow) * D_MODEL) + acol;         // B rows 0..127
    const char* gB1 = (const char*)(W  + (size_t)(n0 + 128 + arow) * D_MODEL) + acol;   // B rows 128..255
    const uint32_t sA  = smb + arow * G_RS + acol;
    const uint32_t sB0 = smb + G_B + arow * G_RS + acol;
    const uint32_t sB1 = sB0 + 128 * G_RS;

#define ISSUE(KT_, ST_) do { \
        const uint32_t so = (uint32_t)(ST_) * G_STAGE; \
        const int go = (KT_) * 64; \
        cpa16(so + sA,         gAh + go); \
        cpa16(so + sA + G_AL,  gAl + go); \
        cpa16(so + sB0,        gB0 + go); \
        cpa16(so + sB1,        gB1 + go); \
        CP_COMMIT(); \
    } while (0)

    float acc[4][4][4];
#pragma unroll
    for (int i = 0; i < 4; i++)
#pragma unroll
        for (int j = 0; j < 4; j++)
#pragma unroll
            for (int k = 0; k < 4; k++) acc[i][j][k] = 0.f;

    ISSUE(0, 0);
    ISSUE(1, 1);

    const int KT = D_MODEL / 32;   // 32
    for (int kt = 0; kt < KT; kt++) {
        if (kt + 1 < KT) CP_WAIT1(); else CP_WAIT0();
        __syncthreads();
        // safe with 3 stages + <=1-iter warp skew
        if (kt + 2 < KT) ISSUE(kt + 2, (kt + 2) % G_NSTAGE);

        const uint32_t stb = smb + (kt % G_NSTAGE) * G_STAGE;
#pragma unroll
        for (int kk = 0; kk < 2; kk++) {
            uint32_t ah[4][4], al[4][4], bh[2][4];
#pragma unroll
            for (int mi = 0; mi < 4; mi++) {
                uint32_t a = stb + (wm * 64 + mi * 16 + (lane & 15)) * G_RS
                           + kk * 32 + (lane >> 4) * 16;
                ldsm4(ah[mi], a);
                ldsm4(al[mi], a + G_AL);
            }
#pragma unroll
            for (int L = 0; L < 2; L++) {
                uint32_t a = stb + G_B
                           + (wn * 32 + L * 16 + (lane & 7) + ((lane >> 4) & 1) * 8) * G_RS
                           + kk * 32 + ((lane >> 3) & 1) * 16;
                ldsm4(bh[L], a);
            }
            // hi sweep (16 independent MMAs), then lo sweep
#pragma unroll
            for (int mi = 0; mi < 4; mi++)
#pragma unroll
                for (int nf = 0; nf < 4; nf++)
                    mma16816(acc[mi][nf], ah[mi], &bh[nf >> 1][(nf & 1) * 2]);
#pragma unroll
            for (int mi = 0; mi < 4; mi++)
#pragma unroll
                for (int nf = 0; nf < 4; nf++)
                    mma16816(acc[mi][nf], al[mi], &bh[nf >> 1][(nf & 1) * 2]);
        }
    }

    // epilogue
#pragma unroll
    for (int mi = 0; mi < 4; mi++)
#pragma unroll
        for (int nf = 0; nf < 4; nf++) {
            const int row0 = m0 + wm * 64 + mi * 16 + (lane >> 2);
            const int col  = n0 + wn * 32 + nf * 8 + 2 * (lane & 3);
            float v0 = acc[mi][nf][0], v1 = acc[mi][nf][1];
            float v2 = acc[mi][nf][2], v3 = acc[mi][nf][3];
            if (mode >= 2) {  // RoPE
                const int p = (col & 63) >> 1;
                const int pos0 = tp[row0 & (SEQ - 1)];
                const int pos1 = tp[(row0 + 8) & (SEQ - 1)];
                const float c0 = g_cos[pos0 * 32 + p], s0 = g_sin[pos0 * 32 + p];
                const float c1 = g_cos[pos1 * 32 + p], s1 = g_sin[pos1 * 32 + p];
                float e0 = v0 * c0 - v1 * s0, o0 = v1 * c0 + v0 * s0;
                float e1 = v2 * c1 - v3 * s1, o1 = v3 * c1 + v2 * s1;
                v0 = e0; v1 = o0; v2 = e1; v3 = o1;
                if (mode == 2) { v0 *= 0.125f; v1 *= 0.125f; v2 *= 0.125f; v3 *= 0.125f; }
            }
            if (mode == 0) {
                *(float2*)(Cf + (size_t)row0 * D_MODEL + col)       = make_float2(v0, v1);
                *(float2*)(Cf + (size_t)(row0 + 8) * D_MODEL + col) = make_float2(v2, v3);
            } else {
                const int hh = col >> 6, d = col & 63;
                const int bb = row0 >> 11, ss = row0 & (SEQ - 1);
                size_t i0 = ((size_t)(bb * N_HEADS + hh) * SEQ + ss) * D_KV + d;
                size_t i1 = i0 + 8 * D_KV;
                if (mode == 2) {
                    uint32_t h0, l0, h1, l1;
                    packhl(v0, v1, h0, l0);
                    packhl(v2, v3, h1, l1);
                    *(uint32_t*)(Qh + i0) = h0; *(uint32_t*)(Ql + i0) = l0;
                    *(uint32_t*)(Qh + i1) = h1; *(uint32_t*)(Ql + i1) = l1;
                } else if (mode == 3) {
                    *(uint32_t*)(Kh + i0) = pack1(v0, v1);
                    *(uint32_t*)(Kh + i1) = pack1(v2, v3);
                } else {
                    *(uint32_t*)(Vh + i0) = pack1(v0, v1);
                    *(uint32_t*)(Vh + i1) = pack1(v2, v3);
                }
            }
        }
#undef ISSUE
}

// ---------------- tensor-core flash attention (causal, shifted-exp softmax) --
// block 256 thr = 8 warps, each warp 16 q-rows; key tiles of 64.
#define A_RS    144                 // 64 fp16 + pad
#define A_KT    (64*A_RS)           // 9216
#define A_STAGE (2*A_KT)            // 18432 (Kh, Vh)
#define QL_OFF  18432               // Q lo tile offset (128*144)
#define ST_OFF  36864               // KV stages start

__global__ __launch_bounds__(256, 1)
void attn_mma(const half* __restrict__ Qh_, const half* __restrict__ Ql_,
              const half* __restrict__ Kh_, const half* __restrict__ Vh_,
              half* __restrict__ Oh_, half* __restrict__ Ol_)
{
    extern __shared__ char sm[];
    const uint32_t smb = (uint32_t)__cvta_generic_to_shared(sm);
    const int tid = threadIdx.x, lane = tid & 31, wid = tid >> 5;
    const int qt = gridDim.x - 1 - blockIdx.x;      // heavy blocks first
    const int q0 = qt * 128;
    const int h = blockIdx.y, b = blockIdx.z;
    const size_t hb = (size_t)(b * N_HEADS + h) * SEQ * D_KV;
    const int nt = 2 * qt + 2;

    const half* Qh = Qh_ + hb; const half* Ql = Ql_ + hb;
    const half* Kh = Kh_ + hb; const half* Vh = Vh_ + hb;

    // load Q tile (hi+lo)
    {
        const int r = tid >> 1;
        const char* gqh = (const char*)(Qh + (size_t)(q0 + r) * D_KV);
        const char* gql = (const char*)(Ql + (size_t)(q0 + r) * D_KV);
        char* sq = sm + r * A_RS;
#pragma unroll
        for (int i = 0; i < 4; i++) {
            const int c = (tid & 1) * 64 + i * 16;
            *(uint4*)(sq + c)          = *(const uint4*)(gqh + c);
            *(uint4*)(sq + QL_OFF + c) = *(const uint4*)(gql + c);
        }
    }

    // KV loader mapping: 4 threads per row, 32B each (row = 128B)
    const int kr = tid >> 2;
    const int kc = (tid & 3) * 32;
    uint4 kbuf[2][2];
#define KV_LOAD(KT_) do { \
        const size_t roff = (size_t)((KT_) * 64 + kr) * D_KV; \
        const char* t0 = (const char*)(Kh + roff); \
        const char* t1 = (const char*)(Vh + roff); \
        kbuf[0][0] = *(const uint4*)(t0 + kc); kbuf[0][1] = *(const uint4*)(t0 + kc + 16); \
        kbuf[1][0] = *(const uint4*)(t1 + kc); kbuf[1][1] = *(const uint4*)(t1 + kc + 16); \
    } while (0)
#define KV_STORE(ST_) do { \
        char* dst = sm + ST_OFF + (ST_) * A_STAGE + kr * A_RS + kc; \
        *(uint4*)(dst)             = kbuf[0][0]; \
        *(uint4*)(dst + 16)        = kbuf[0][1]; \
        *(uint4*)(dst + A_KT)      = kbuf[1][0]; \
        *(uint4*)(dst + A_KT + 16) = kbuf[1][1]; \
    } while (0)

    KV_LOAD(0);
    KV_STORE(0);
    __syncthreads();

    // Q fragments
    uint32_t qh[4][4], ql[4][4];
#pragma unroll
    for (int kk = 0; kk < 4; kk++) {
        uint32_t a = smb + (wid * 16 + (lane & 15)) * A_RS + kk * 32 + (lane >> 4) * 16;
        ldsm4(qh[kk], a);
        ldsm4(ql[kk], a + QL_OFF);
    }

    float oacc[8][4];
#pragma unroll
    for (int i = 0; i < 8; i++)
#pragma unroll
        for (int j = 0; j < 4; j++) oacc[i][j] = 0.f;
    float ls0 = 0.f, ls1 = 0.f;
    const int wr0 = q0 + wid * 16;

    for (int kt = 0; kt < nt; kt++) {
        if (kt + 1 < nt) KV_LOAD(kt + 1);
        const uint32_t stb = smb + ST_OFF + (kt & 1) * A_STAGE;
        const int kbase = kt * 64;

        if (kbase <= wr0 + 15) {
            float sacc[8][4];
#pragma unroll
            for (int i = 0; i < 8; i++)
#pragma unroll
                for (int j = 0; j < 4; j++) sacc[i][j] = 0.f;

            // S = (Qh+Ql) Kh^T  -- hi sweep then lo sweep per kk
#pragma unroll
            for (int kk = 0; kk < 4; kk++) {
                uint32_t kbh[4][4];
#pragma unroll
                for (int L = 0; L < 4; L++) {
                    uint32_t a = stb + (L * 16 + (lane & 7) + ((lane >> 4) & 1) * 8) * A_RS
                               + kk * 32 + ((lane >> 3) & 1) * 16;
                    ldsm4(kbh[L], a);
                }
#pragma unroll
                for (int nf = 0; nf < 8; nf++)
                    mma16816(sacc[nf], qh[kk], &kbh[nf >> 1][(nf & 1) * 2]);
#pragma unroll
                for (int nf = 0; nf < 8; nf++)
                    mma16816(sacc[nf], ql[kk], &kbh[nf >> 1][(nf & 1) * 2]);
            }

            // mask + shifted exp (p = e^(s-6); shift cancels in normalization)
            const bool needm = (kbase + 63 > wr0);
#pragma unroll
            for (int nf = 0; nf < 8; nf++)
#pragma unroll
                for (int j = 0; j < 4; j++) {
                    float p = __expf(sacc[nf][j] - 6.0f);
                    if (needm) {
                        const int key = kbase + nf * 8 + 2 * (lane & 3) + (j & 1);
                        const int row = wr0 + (lane >> 2) + (j >> 1) * 8;
                        if (key > row) p = 0.f;
                    }
                    sacc[nf][j] = p;
                    if (j < 2) ls0 += p; else ls1 += p;
                }

            // O += (Ph+Pl) Vh  -- hi sweep then lo sweep per kk2
#pragma unroll
            for (int kk2 = 0; kk2 < 4; kk2++) {
                uint32_t vh[4][4];
#pragma unroll
                for (int dL = 0; dL < 4; dL++) {
                    uint32_t a = stb + A_KT
                               + (kk2 * 16 + (lane & 7) + ((lane >> 3) & 1) * 8) * A_RS
                               + dL * 32 + ((lane >> 4) & 1) * 16;
                    ldsm4t(vh[dL], a);
                }
                uint32_t ph[4], pl[4];
                packhl(sacc[2*kk2][0],   sacc[2*kk2][1],   ph[0], pl[0]);
                packhl(sacc[2*kk2][2],   sacc[2*kk2][3],   ph[1], pl[1]);
                packhl(sacc[2*kk2+1][0], sacc[2*kk2+1][1], ph[2], pl[2]);
                packhl(sacc[2*kk2+1][2], sacc[2*kk2+1][3], ph[3], pl[3]);
#pragma unroll
                for (int df = 0; df < 8; df++)
                    mma16816(oacc[df], ph, &vh[df >> 1][(df & 1) * 2]);
#pragma unroll
                for (int df = 0; df < 8; df++)
                    mma16816(oacc[df], pl, &vh[df >> 1][(df & 1) * 2]);
            }
        }

        if (kt + 1 < nt) KV_STORE((kt + 1) & 1);
        __syncthreads();
    }

    // reduce row sums across quad
    ls0 += __shfl_xor_sync(0xffffffffu, ls0, 1);
    ls0 += __shfl_xor_sync(0xffffffffu, ls0, 2);
    ls1 += __shfl_xor_sync(0xffffffffu, ls1, 1);
    ls1 += __shfl_xor_sync(0xffffffffu, ls1, 2);
    const float inv0 = 1.f / ls0, inv1 = 1.f / ls1;

    const int row0 = q0 + wid * 16 + (lane >> 2);
#pragma unroll
    for (int df = 0; df < 8; df++) {
        const int d = df * 8 + 2 * (lane & 3);
        const float v0 = oacc[df][0] * inv0, v1 = oacc[df][1] * inv0;
        const float v2 = oacc[df][2] * inv1, v3 = oacc[df][3] * inv1;
        const size_t i0 = (size_t)(b * SEQ + row0) * D_MODEL + h * D_KV + d;
        const size_t i1 = i0 + (size_t)8 * D_MODEL;
        uint32_t h0, l0, h1, l1;
        packhl(v0, v1, h0, l0);
        packhl(v2, v3, h1, l1);
        *(uint32_t*)(Oh_ + i0) = h0; *(uint32_t*)(Ol_ + i0) = l0;
        *(uint32_t*)(Oh_ + i1) = h1; *(uint32_t*)(Ol_ + i1) = l1;
    }
}

// ---------------- host launcher ----------------------------------------------
extern "C" void kernel_launch(void* const* d_in, const int* in_sizes, int n_in,
                              void* d_out, int out_size)
{
    const float* x  = (const float*)d_in[0];
    const float* wq = (const float*)d_in[1];
    const float* wk = (const float*)d_in[2];
    const float* wv = (const float*)d_in[3];
    const float* wo = (const float*)d_in[4];
    const int*   tp = (const int*)d_in[5];
    float* out = (float*)d_out;

    half *xh, *xl, *wqh, *wkh, *wvh, *woh;
    half *Qh, *Ql, *Kh, *Vh, *Oh, *Ol;
    cudaGetSymbolAddress((void**)&xh, g_xh);   cudaGetSymbolAddress((void**)&xl, g_xl);
    cudaGetSymbolAddress((void**)&wqh, g_wqh); cudaGetSymbolAddress((void**)&wkh, g_wkh);
    cudaGetSymbolAddress((void**)&wvh, g_wvh); cudaGetSymbolAddress((void**)&woh, g_woh);
    cudaGetSymbolAddress((void**)&Qh, g_Qh);   cudaGetSymbolAddress((void**)&Ql, g_Ql);
    cudaGetSymbolAddress((void**)&Kh, g_Kh);   cudaGetSymbolAddress((void**)&Vh, g_Vh);
    cudaGetSymbolAddress((void**)&Oh, g_Oh);   cudaGetSymbolAddress((void**)&Ol, g_Ol);

    const int gemm_smem = G_NSTAGE * G_STAGE;                 // 122880
    const int attn_smem = ST_OFF + 2 * A_STAGE;               // 73728
    cudaFuncSetAttribute(gemm_mma, cudaFuncAttributeMaxDynamicSharedMemorySize, gemm_smem);
    cudaFuncSetAttribute(attn_mma, cudaFuncAttributeMaxDynamicSharedMemorySize, attn_smem);

    // splits / converts / tables (3 launches)
    split_kernel<<<M_TOTAL * D_MODEL / 1024, 256>>>(x, xh, xl, M_TOTAL * D_MODEL);
    cvtw_kernel<<<dim3(D_MODEL * D_MODEL / 1024, 4), 256>>>(wq, wk, wv, wo,
                                                            wqh, wkh, wvh, woh);
    rope_table_kernel<<<SEQ * 32 / 256, 256>>>();

    // fused QKV projections (one launch, 512 threads)
    dim3 qkvgrid(D_MODEL / 256, M_TOTAL / 128, 3);   // (4, 32, 3)
    gemm_mma<<<qkvgrid, 512, gemm_smem>>>(xh, xl, wqh, wkh, wvh,
                                          nullptr, Qh, Ql, Kh, Vh, tp, 1);

    // attention
    dim3 agrid(SEQ / 128, N_HEADS, BATCH);           // (16,16,2)
    attn_mma<<<agrid, 256, attn_smem>>>(Qh, Ql, Kh, Vh, Oh, Ol);

    // output projection
    dim3 ogrid(D_MODEL / 256, M_TOTAL / 128, 1);
    gemm_mma<<<ogrid, 512, gemm_smem>>>(Oh, Ol, woh, nullptr, nullptr,
                                        out, nullptr, nullptr, nullptr, nullptr, tp, 0);
}